// round 4
// baseline (speedup 1.0000x reference)
#include <cuda_runtime.h>
#include <cstdint>
#include <cstddef>

#define MEMB   8
#define BATCHI 4096
#define E_DIM  512
#define H_DIM  1024
#define V_DIM  4096
#define ROWS   (MEMB * BATCHI)   // 32768

// ---------------- scratch (device globals: allocation-free) ----------------
__device__ float g_xr [(size_t)ROWS * E_DIM];          // tf32-rounded x
__device__ float g_w1r[(size_t)MEMB * E_DIM * H_DIM];  // tf32-rounded W1
__device__ float g_w2r[(size_t)MEMB * H_DIM * V_DIM];  // tf32-rounded W2
__device__ float g_h  [(size_t)ROWS * H_DIM];          // hidden activations

// ---------------- helpers ----------------
__device__ __forceinline__ float tf32_rna(float x) {
    uint32_t u;
    asm("cvt.rna.tf32.f32 %0, %1;" : "=r"(u) : "f"(x));
    return __uint_as_float(u);
}
__device__ __forceinline__ uint32_t smem_u32(const void* p) {
    uint32_t a;
    asm("{ .reg .u64 t; cvta.to.shared.u64 t, %1; cvt.u32.u64 %0, t; }"
        : "=r"(a) : "l"(p));
    return a;
}
__device__ __forceinline__ void cp16(uint32_t s, const void* g) {
    asm volatile("cp.async.cg.shared.global [%0], [%1], 16;" :: "r"(s), "l"(g));
}
__device__ __forceinline__ void cp_commit() {
    asm volatile("cp.async.commit_group;" ::: "memory");
}
__device__ __forceinline__ void cp_wait2() {
    asm volatile("cp.async.wait_group 2;" ::: "memory");
}
__device__ __forceinline__ void mma_tf32(float (&d)[4], const uint32_t (&a)[4],
                                         const uint32_t (&b)[2]) {
    asm volatile(
        "mma.sync.aligned.m16n8k8.row.col.f32.tf32.tf32.f32 "
        "{%0,%1,%2,%3}, {%4,%5,%6,%7}, {%8,%9}, {%0,%1,%2,%3};\n"
        : "+f"(d[0]), "+f"(d[1]), "+f"(d[2]), "+f"(d[3])
        : "r"(a[0]), "r"(a[1]), "r"(a[2]), "r"(a[3]), "r"(b[0]), "r"(b[1]));
}

// ---------------- tiling ----------------
#define BM   128
#define BN   256
#define BK   16
#define NTHREADS 512
#define STAGES 4
#define AST  20        // As row stride (floats), conflict-free
#define BST  264       // Bs row stride (floats), 264 mod 32 == 8 -> conflict-free
#define A_FLOATS (BM * AST)         // 2560
#define B_FLOATS (BK * BST)         // 4224
#define STAGE_FLOATS (A_FLOATS + B_FLOATS)   // 6784
#define STAGE_BYTES  (STAGE_FLOATS * 4)      // 27136
#define SMEM_TOTAL   (STAGES * STAGE_BYTES)  // 108544
#define A_CHUNKS (BM * BK / 4)      // 512 16B chunks
#define B_CHUNKS (BK * BN / 4)      // 1024

// issue one stage worth of cp.async (3 chunks / thread, 512 threads)
__device__ __forceinline__ void load_stage(uint32_t sbase_bytes, int st,
                                           const float* __restrict__ Ag,
                                           const float* __restrict__ Bg,
                                           int K, int Ntot, int tid) {
    const uint32_t sA = sbase_bytes + st * STAGE_BYTES;
    const uint32_t sB = sA + A_FLOATS * 4;
#pragma unroll
    for (int j = 0; j < (A_CHUNKS + B_CHUNKS) / NTHREADS; j++) {
        const int c = tid + j * NTHREADS;
        if (c < A_CHUNKS) {
            const int row = c >> 2, q = c & 3;      // 4 chunks per row (BK=16)
            cp16(sA + (uint32_t)(row * AST * 4 + q * 16),
                 Ag + (size_t)row * K + q * 4);
        } else {
            const int b = c - A_CHUNKS;
            const int k = b >> 6, q = b & 63;       // 64 chunks per k-row (BN=256)
            cp16(sB + (uint32_t)(k * BST * 4 + q * 16),
                 Bg + (size_t)k * Ntot + q * 4);
        }
    }
}

// ---------------- GEMM: C[row,n] = sum_k A[row,k]*W[m,k,n] + bias[m,n] ----------
// 512 threads = 16 warps (2m x 8n), warp tile 64x32, 4-stage cp.async pipeline.
__launch_bounds__(NTHREADS, 1)
__global__ void gemm_mma(const float* __restrict__ A,
                         const float* __restrict__ W,
                         const float* __restrict__ bias,
                         float* __restrict__ C,
                         int K, int Ntot, int NT) {
    extern __shared__ __align__(16) float smf[];
    const uint32_t sbase = smem_u32(smf);

    const int tid  = threadIdx.x;
    const int lane = tid & 31;
    const int warp = tid >> 5;
    const int wm   = warp >> 3;      // 0..1
    const int wn   = warp & 7;       // 0..7
    const int g    = lane >> 2;      // 0..7
    const int r    = lane & 3;       // 0..3

    const int brow   = blockIdx.y * BM;
    const int bcol   = blockIdx.x * BN;
    const int member = brow >> 12;

    const float* Ag0 = A + (size_t)brow * K;
    const float* Bg0 = W + (size_t)member * K * Ntot + bcol;

    float acc[4][4][4];
#pragma unroll
    for (int i = 0; i < 4; i++)
#pragma unroll
        for (int j = 0; j < 4; j++)
#pragma unroll
            for (int c = 0; c < 4; c++) acc[i][j][c] = 0.f;

    // prologue: stages 0..2
#pragma unroll
    for (int s = 0; s < STAGES - 1; s++) {
        load_stage(sbase, s, Ag0 + s * BK, Bg0 + (size_t)s * BK * Ntot,
                   K, Ntot, tid);
        cp_commit();
    }

    for (int t = 0; t < NT; t++) {
        cp_wait2();
        __syncthreads();

        const int u = t + STAGES - 1;
        if (u < NT) {
            load_stage(sbase, u & (STAGES - 1), Ag0 + u * BK,
                       Bg0 + (size_t)u * BK * Ntot, K, Ntot, tid);
        }
        cp_commit();

        const float* As = smf + (t & (STAGES - 1)) * STAGE_FLOATS;
        const float* Bs = As + A_FLOATS;

#pragma unroll
        for (int ks = 0; ks < 2; ks++) {
            uint32_t af[4][4];
            uint32_t bf[4][2];
#pragma unroll
            for (int mt = 0; mt < 4; mt++) {
                const float* ap = &As[(wm * 64 + mt * 16 + g) * AST + ks * 8 + r];
                af[mt][0] = __float_as_uint(ap[0]);
                af[mt][1] = __float_as_uint(ap[8 * AST]);
                af[mt][2] = __float_as_uint(ap[4]);
                af[mt][3] = __float_as_uint(ap[8 * AST + 4]);
            }
#pragma unroll
            for (int nt = 0; nt < 4; nt++) {
                const float* bp = &Bs[(ks * 8 + r) * BST + wn * 32 + nt * 8 + g];
                bf[nt][0] = __float_as_uint(bp[0]);
                bf[nt][1] = __float_as_uint(bp[4 * BST]);
            }
#pragma unroll
            for (int mt = 0; mt < 4; mt++)
#pragma unroll
                for (int nt = 0; nt < 4; nt++)
                    mma_tf32(acc[mt][nt], af[mt], bf[nt]);
        }
    }

    // epilogue: bias + store
    const float* bm = bias + (size_t)member * Ntot + bcol;
#pragma unroll
    for (int mt = 0; mt < 4; mt++) {
        const int row0 = brow + wm * 64 + mt * 16 + g;
#pragma unroll
        for (int nt = 0; nt < 4; nt++) {
            const int col0 = bcol + wn * 32 + nt * 8 + r * 2;
            const float bx0 = __ldg(bm + (col0 - bcol));
            const float bx1 = __ldg(bm + (col0 - bcol) + 1);
            float2 v0, v1;
            v0.x = acc[mt][nt][0] + bx0;
            v0.y = acc[mt][nt][1] + bx1;
            v1.x = acc[mt][nt][2] + bx0;
            v1.y = acc[mt][nt][3] + bx1;
            *(float2*)(C + (size_t)row0 * Ntot + col0) = v0;
            *(float2*)(C + (size_t)(row0 + 8) * Ntot + col0) = v1;
        }
    }
}

// ---------------- pre-pass: elementwise tf32 RNA rounding ----------------
__global__ void round_kernel(const float* __restrict__ in,
                             float* __restrict__ out, int n4) {
    int i = blockIdx.x * blockDim.x + threadIdx.x;
    if (i >= n4) return;
    float4 v = ((const float4*)in)[i];
    v.x = tf32_rna(v.x); v.y = tf32_rna(v.y);
    v.z = tf32_rna(v.z); v.w = tf32_rna(v.w);
    ((float4*)out)[i] = v;
}

// ---------------- fused LayerNorm + SiLU (+ tf32 rounding of h) -------------
__launch_bounds__(256)
__global__ void ln_silu_kernel(const float* __restrict__ ln_w,
                               const float* __restrict__ ln_b) {
    const int row = blockIdx.x;
    const int m   = row >> 12;
    float* hp = g_h + (size_t)row * H_DIM;
    const int t = threadIdx.x;

    float4 x = *(const float4*)(hp + t * 4);
    float s = x.x + x.y + x.z + x.w;
    float q = x.x * x.x + x.y * x.y + x.z * x.z + x.w * x.w;
#pragma unroll
    for (int o = 16; o; o >>= 1) {
        s += __shfl_xor_sync(0xffffffffu, s, o);
        q += __shfl_xor_sync(0xffffffffu, q, o);
    }
    __shared__ float rs[8], rq[8];
    if ((t & 31) == 0) { rs[t >> 5] = s; rq[t >> 5] = q; }
    __syncthreads();
    s = rs[0] + rs[1] + rs[2] + rs[3] + rs[4] + rs[5] + rs[6] + rs[7];
    q = rq[0] + rq[1] + rq[2] + rq[3] + rq[4] + rq[5] + rq[6] + rq[7];

    const float mu  = s * (1.0f / H_DIM);
    const float var = q * (1.0f / H_DIM) - mu * mu;
    const float inv = rsqrtf(var + 1e-5f);

    const float4 w = *(const float4*)(ln_w + (size_t)m * H_DIM + t * 4);
    const float4 b = *(const float4*)(ln_b + (size_t)m * H_DIM + t * 4);

    float4 y; float v;
    v = (x.x - mu) * inv * w.x + b.x; y.x = tf32_rna(v / (1.f + __expf(-v)));
    v = (x.y - mu) * inv * w.y + b.y; y.y = tf32_rna(v / (1.f + __expf(-v)));
    v = (x.z - mu) * inv * w.z + b.z; y.z = tf32_rna(v / (1.f + __expf(-v)));
    v = (x.w - mu) * inv * w.w + b.w; y.w = tf32_rna(v / (1.f + __expf(-v)));
    *(float4*)(hp + t * 4) = y;
}

// ---------------- launch ----------------
extern "C" void kernel_launch(void* const* d_in, const int* in_sizes, int n_in,
                              void* d_out, int out_size) {
    const float* x  = (const float*)d_in[0];
    const float* W1 = (const float*)d_in[1];
    const float* b1 = (const float*)d_in[2];
    const float* lw = (const float*)d_in[3];
    const float* lb = (const float*)d_in[4];
    const float* W2 = (const float*)d_in[5];
    const float* b2 = (const float*)d_in[6];
    float* out = (float*)d_out;

    float *xr, *w1r, *w2r, *h;
    cudaGetSymbolAddress((void**)&xr,  g_xr);
    cudaGetSymbolAddress((void**)&w1r, g_w1r);
    cudaGetSymbolAddress((void**)&w2r, g_w2r);
    cudaGetSymbolAddress((void**)&h,   g_h);

    cudaFuncSetAttribute(gemm_mma, cudaFuncAttributeMaxDynamicSharedMemorySize,
                         SMEM_TOTAL);

    // pre-pass: tf32 RNA rounding
    round_kernel<<<(ROWS * E_DIM / 4 + 511) / 512, 512>>>(x, xr,
                                                          ROWS * E_DIM / 4);
    round_kernel<<<(MEMB * E_DIM * H_DIM / 4 + 511) / 512, 512>>>(
        W1, w1r, MEMB * E_DIM * H_DIM / 4);
    round_kernel<<<(MEMB * H_DIM * V_DIM / 4 + 511) / 512, 512>>>(
        W2, w2r, MEMB * H_DIM * V_DIM / 4);

    // GEMM1: [32768,512] x [8: 512->1024] -> h (+b1)
    gemm_mma<<<dim3(H_DIM / BN, ROWS / BM), NTHREADS, SMEM_TOTAL>>>(
        xr, w1r, b1, h, E_DIM, H_DIM, E_DIM / BK);
    // LayerNorm + SiLU (+ tf32 rounding)
    ln_silu_kernel<<<ROWS, 256>>>(lw, lb);
    // GEMM2: [32768,1024] x [8: 1024->4096] -> out (+b2)
    gemm_mma<<<dim3(V_DIM / BN, ROWS / BM), NTHREADS, SMEM_TOTAL>>>(
        h, w2r, b2, out, H_DIM, V_DIM, H_DIM / BK);
}

// round 5
// speedup vs baseline: 1.7752x; 1.7752x over previous
#include <cuda_runtime.h>
#include <cuda_fp16.h>
#include <cstdint>
#include <cstddef>

#define MEMB   8
#define BATCHI 4096
#define E_DIM  512
#define H_DIM  1024
#define V_DIM  4096
#define ROWS   (MEMB * BATCHI)   // 32768

// ---------------- scratch (device globals: allocation-free) ----------------
__device__ __half g_xh [(size_t)ROWS * E_DIM];          // fp16 x
__device__ __half g_w1h[(size_t)MEMB * E_DIM * H_DIM];  // fp16 W1
__device__ __half g_w2h[(size_t)MEMB * H_DIM * V_DIM];  // fp16 W2
__device__ float  g_h  [(size_t)ROWS * H_DIM];          // fp32 hidden (GEMM1 out)
__device__ __half g_hh [(size_t)ROWS * H_DIM];          // fp16 hidden (GEMM2 in)

// ---------------- helpers ----------------
__device__ __forceinline__ uint32_t smem_u32(const void* p) {
    uint32_t a;
    asm("{ .reg .u64 t; cvta.to.shared.u64 t, %1; cvt.u32.u64 %0, t; }"
        : "=r"(a) : "l"(p));
    return a;
}
__device__ __forceinline__ void cp16(uint32_t s, const void* g) {
    asm volatile("cp.async.cg.shared.global [%0], [%1], 16;" :: "r"(s), "l"(g));
}
__device__ __forceinline__ void cp_commit() {
    asm volatile("cp.async.commit_group;" ::: "memory");
}
__device__ __forceinline__ void cp_wait2() {
    asm volatile("cp.async.wait_group 2;" ::: "memory");
}
__device__ __forceinline__ void ldsm_x4(uint32_t (&r)[4], uint32_t addr) {
    asm volatile("ldmatrix.sync.aligned.m8n8.x4.shared.b16 {%0,%1,%2,%3}, [%4];"
                 : "=r"(r[0]), "=r"(r[1]), "=r"(r[2]), "=r"(r[3]) : "r"(addr));
}
__device__ __forceinline__ void ldsm_x2_t(uint32_t (&r)[2], uint32_t addr) {
    asm volatile("ldmatrix.sync.aligned.m8n8.x2.trans.shared.b16 {%0,%1}, [%2];"
                 : "=r"(r[0]), "=r"(r[1]) : "r"(addr));
}
__device__ __forceinline__ void mma_f16(float (&d)[4], const uint32_t (&a)[4],
                                        const uint32_t (&b)[2]) {
    asm volatile(
        "mma.sync.aligned.m16n8k16.row.col.f32.f16.f16.f32 "
        "{%0,%1,%2,%3}, {%4,%5,%6,%7}, {%8,%9}, {%0,%1,%2,%3};\n"
        : "+f"(d[0]), "+f"(d[1]), "+f"(d[2]), "+f"(d[3])
        : "r"(a[0]), "r"(a[1]), "r"(a[2]), "r"(a[3]), "r"(b[0]), "r"(b[1]));
}

// ---------------- tiling ----------------
#define BM   128
#define BN   256
#define BK   32            // fp16 k-depth per tile
#define NTHREADS 256
#define STAGES 4
#define A_ROW_B  80        // A smem row stride bytes (32 halfs + pad) conflict-free
#define B_ROW_B  528       // B smem row stride bytes (256 halfs + pad) conflict-free
#define A_ST_B   (BM * A_ROW_B)              // 10240
#define B_ST_B   (BK * B_ROW_B)              // 16896
#define STAGE_B  (A_ST_B + B_ST_B)           // 27136
#define SMEM_TOTAL (STAGES * STAGE_B)        // 108544
#define A_CHUNKS (BM * BK * 2 / 16)          // 512
#define B_CHUNKS (BK * BN * 2 / 16)          // 1024

// one stage of cp.async: 6 chunks/thread @ 256 threads
__device__ __forceinline__ void load_stage(uint32_t sbase, int st,
                                           const __half* __restrict__ Ag,
                                           const __half* __restrict__ Bg,
                                           int K, int Ntot, int tid) {
    const uint32_t sA = sbase + st * STAGE_B;
    const uint32_t sB = sA + A_ST_B;
#pragma unroll
    for (int j = 0; j < (A_CHUNKS + B_CHUNKS) / NTHREADS; j++) {
        const int c = tid + j * NTHREADS;
        if (c < A_CHUNKS) {
            const int row = c >> 2, q = c & 3;        // 4 chunks per A row
            cp16(sA + (uint32_t)(row * A_ROW_B + q * 16),
                 Ag + (size_t)row * K + q * 8);
        } else {
            const int b = c - A_CHUNKS;
            const int k = b >> 5, q = b & 31;         // 32 chunks per B row
            cp16(sB + (uint32_t)(k * B_ROW_B + q * 16),
                 Bg + (size_t)k * Ntot + q * 8);
        }
    }
}

// -------- GEMM: C[row,n] = sum_k A[row,k]*W[m,k,n] + bias[m,n] (fp16 in, fp32 out)
// 256 threads = 8 warps (2m x 4n), warp tile 64x64, ldmatrix + m16n8k16.
__launch_bounds__(NTHREADS, 1)
__global__ void gemm_f16(const __half* __restrict__ A,
                         const __half* __restrict__ W,
                         const float* __restrict__ bias,
                         float* __restrict__ C,
                         int K, int Ntot, int NT) {
    extern __shared__ __align__(16) char smc[];
    const uint32_t sbase = smem_u32(smc);

    const int tid  = threadIdx.x;
    const int lane = tid & 31;
    const int warp = tid >> 5;
    const int wm   = warp >> 2;      // 0..1
    const int wn   = warp & 3;       // 0..3
    const int g    = lane >> 2;      // 0..7
    const int r    = lane & 3;       // 0..3

    const int brow   = blockIdx.y * BM;
    const int bcol   = blockIdx.x * BN;
    const int member = brow >> 12;

    const __half* Ag0 = A + (size_t)brow * K;
    const __half* Bg0 = W + (size_t)member * K * Ntot + bcol;

    float acc[4][8][4];
#pragma unroll
    for (int i = 0; i < 4; i++)
#pragma unroll
        for (int j = 0; j < 8; j++)
#pragma unroll
            for (int c = 0; c < 4; c++) acc[i][j][c] = 0.f;

    // per-lane invariant pieces of ldmatrix addresses
    const uint32_t a_lane_off =
        (uint32_t)((lane & 15) * A_ROW_B + (lane >> 4) * 16);
    const uint32_t b_lane_off = (uint32_t)((lane & 15) * B_ROW_B);

#pragma unroll
    for (int s = 0; s < STAGES - 1; s++) {
        load_stage(sbase, s, Ag0 + s * BK, Bg0 + (size_t)s * BK * Ntot,
                   K, Ntot, tid);
        cp_commit();
    }

    for (int t = 0; t < NT; t++) {
        cp_wait2();
        __syncthreads();

        const int u = t + STAGES - 1;
        if (u < NT) {
            load_stage(sbase, u & (STAGES - 1), Ag0 + u * BK,
                       Bg0 + (size_t)u * BK * Ntot, K, Ntot, tid);
        }
        cp_commit();

        const uint32_t sA = sbase + (t & (STAGES - 1)) * STAGE_B;
        const uint32_t sB = sA + A_ST_B;

#pragma unroll
        for (int ks = 0; ks < 2; ks++) {
            uint32_t af[4][4];
            uint32_t bf[8][2];
#pragma unroll
            for (int mt = 0; mt < 4; mt++) {
                ldsm_x4(af[mt], sA + (uint32_t)((wm * 64 + mt * 16) * A_ROW_B +
                                                ks * 32) + a_lane_off);
            }
#pragma unroll
            for (int nt = 0; nt < 8; nt++) {
                ldsm_x2_t(bf[nt], sB + (uint32_t)(ks * 16 * B_ROW_B +
                                                  (wn * 64 + nt * 8) * 2) +
                                      b_lane_off);
            }
#pragma unroll
            for (int mt = 0; mt < 4; mt++)
#pragma unroll
                for (int nt = 0; nt < 8; nt++)
                    mma_f16(acc[mt][nt], af[mt], bf[nt]);
        }
    }

    // epilogue: bias + store fp32
    const float* bm = bias + (size_t)member * Ntot + bcol;
#pragma unroll
    for (int mt = 0; mt < 4; mt++) {
        const int row0 = brow + wm * 64 + mt * 16 + g;
#pragma unroll
        for (int nt = 0; nt < 8; nt++) {
            const int col0 = bcol + wn * 64 + nt * 8 + r * 2;
            const float bx0 = __ldg(bm + (col0 - bcol));
            const float bx1 = __ldg(bm + (col0 - bcol) + 1);
            float2 v0, v1;
            v0.x = acc[mt][nt][0] + bx0;
            v0.y = acc[mt][nt][1] + bx1;
            v1.x = acc[mt][nt][2] + bx0;
            v1.y = acc[mt][nt][3] + bx1;
            *(float2*)(C + (size_t)row0 * Ntot + col0) = v0;
            *(float2*)(C + (size_t)(row0 + 8) * Ntot + col0) = v1;
        }
    }
}

// ---------------- pre-pass: fp32 -> fp16 convert (8 elems/thread) ----------
__global__ void f32_to_f16(const float* __restrict__ in,
                           __half* __restrict__ out, int n8) {
    int i = blockIdx.x * blockDim.x + threadIdx.x;
    if (i >= n8) return;
    float4 a = ((const float4*)in)[2 * i];
    float4 b = ((const float4*)in)[2 * i + 1];
    __half2 h[4];
    h[0] = __floats2half2_rn(a.x, a.y);
    h[1] = __floats2half2_rn(a.z, a.w);
    h[2] = __floats2half2_rn(b.x, b.y);
    h[3] = __floats2half2_rn(b.z, b.w);
    ((uint4*)out)[i] = *(uint4*)h;
}

// ------------- fused LayerNorm + SiLU; fp32 in (g_h), fp16 out (g_hh) -------
__launch_bounds__(256)
__global__ void ln_silu_kernel(const float* __restrict__ ln_w,
                               const float* __restrict__ ln_b) {
    const int row = blockIdx.x;
    const int m   = row >> 12;
    const float* hp = g_h + (size_t)row * H_DIM;
    __half* op = g_hh + (size_t)row * H_DIM;
    const int t = threadIdx.x;

    float4 x = *(const float4*)(hp + t * 4);
    float s = x.x + x.y + x.z + x.w;
    float q = x.x * x.x + x.y * x.y + x.z * x.z + x.w * x.w;
#pragma unroll
    for (int o = 16; o; o >>= 1) {
        s += __shfl_xor_sync(0xffffffffu, s, o);
        q += __shfl_xor_sync(0xffffffffu, q, o);
    }
    __shared__ float rs[8], rq[8];
    if ((t & 31) == 0) { rs[t >> 5] = s; rq[t >> 5] = q; }
    __syncthreads();
    s = rs[0] + rs[1] + rs[2] + rs[3] + rs[4] + rs[5] + rs[6] + rs[7];
    q = rq[0] + rq[1] + rq[2] + rq[3] + rq[4] + rq[5] + rq[6] + rq[7];

    const float mu  = s * (1.0f / H_DIM);
    const float var = q * (1.0f / H_DIM) - mu * mu;
    const float inv = rsqrtf(var + 1e-5f);

    const float4 w = *(const float4*)(ln_w + (size_t)m * H_DIM + t * 4);
    const float4 b = *(const float4*)(ln_b + (size_t)m * H_DIM + t * 4);

    float y[4]; float v;
    v = (x.x - mu) * inv * w.x + b.x; y[0] = v / (1.f + __expf(-v));
    v = (x.y - mu) * inv * w.y + b.y; y[1] = v / (1.f + __expf(-v));
    v = (x.z - mu) * inv * w.z + b.z; y[2] = v / (1.f + __expf(-v));
    v = (x.w - mu) * inv * w.w + b.w; y[3] = v / (1.f + __expf(-v));
    __half2 h2[2];
    h2[0] = __floats2half2_rn(y[0], y[1]);
    h2[1] = __floats2half2_rn(y[2], y[3]);
    *(uint2*)(op + t * 4) = *(uint2*)h2;
}

// ---------------- launch ----------------
extern "C" void kernel_launch(void* const* d_in, const int* in_sizes, int n_in,
                              void* d_out, int out_size) {
    const float* x  = (const float*)d_in[0];
    const float* W1 = (const float*)d_in[1];
    const float* b1 = (const float*)d_in[2];
    const float* lw = (const float*)d_in[3];
    const float* lb = (const float*)d_in[4];
    const float* W2 = (const float*)d_in[5];
    const float* b2 = (const float*)d_in[6];
    float* out = (float*)d_out;

    __half *xh, *w1h, *w2h, *hh;
    float* h;
    cudaGetSymbolAddress((void**)&xh,  g_xh);
    cudaGetSymbolAddress((void**)&w1h, g_w1h);
    cudaGetSymbolAddress((void**)&w2h, g_w2h);
    cudaGetSymbolAddress((void**)&h,   g_h);
    cudaGetSymbolAddress((void**)&hh,  g_hh);

    cudaFuncSetAttribute(gemm_f16, cudaFuncAttributeMaxDynamicSharedMemorySize,
                         SMEM_TOTAL);

    // pre-pass: fp32 -> fp16
    f32_to_f16<<<(ROWS * E_DIM / 8 + 255) / 256, 256>>>(x, xh,
                                                        ROWS * E_DIM / 8);
    f32_to_f16<<<(MEMB * E_DIM * H_DIM / 8 + 255) / 256, 256>>>(
        W1, w1h, MEMB * E_DIM * H_DIM / 8);
    f32_to_f16<<<(MEMB * H_DIM * V_DIM / 8 + 255) / 256, 256>>>(
        W2, w2h, MEMB * H_DIM * V_DIM / 8);

    // GEMM1: [32768,512] x [8: 512->1024] -> h (+b1), fp32 out
    gemm_f16<<<dim3(H_DIM / BN, ROWS / BM), NTHREADS, SMEM_TOTAL>>>(
        xh, w1h, b1, h, E_DIM, H_DIM, E_DIM / BK);
    // LayerNorm + SiLU, fp16 out
    ln_silu_kernel<<<ROWS, 256>>>(lw, lb);
    // GEMM2: [32768,1024] x [8: 1024->4096] -> out (+b2)
    gemm_f16<<<dim3(V_DIM / BN, ROWS / BM), NTHREADS, SMEM_TOTAL>>>(
        hh, w2h, b2, out, H_DIM, V_DIM, H_DIM / BK);
}

// round 6
// speedup vs baseline: 1.8567x; 1.0459x over previous
#include <cuda_runtime.h>
#include <cuda_fp16.h>
#include <cstdint>
#include <cstddef>

#define MEMB   8
#define BATCHI 4096
#define E_DIM  512
#define H_DIM  1024
#define V_DIM  4096
#define ROWS   (MEMB * BATCHI)   // 32768

// ---------------- scratch (device globals: allocation-free) ----------------
__device__ __half g_xh [(size_t)ROWS * E_DIM];          // fp16 x
__device__ __half g_w1h[(size_t)MEMB * E_DIM * H_DIM];  // fp16 W1
__device__ __half g_w2h[(size_t)MEMB * H_DIM * V_DIM];  // fp16 W2
__device__ float  g_h  [(size_t)ROWS * H_DIM];          // fp32 hidden (GEMM1 out)
__device__ __half g_hh [(size_t)ROWS * H_DIM];          // fp16 hidden (GEMM2 in)

// ---------------- helpers ----------------
__device__ __forceinline__ uint32_t smem_u32(const void* p) {
    uint32_t a;
    asm("{ .reg .u64 t; cvta.to.shared.u64 t, %1; cvt.u32.u64 %0, t; }"
        : "=r"(a) : "l"(p));
    return a;
}
__device__ __forceinline__ void cp16(uint32_t s, const void* g) {
    asm volatile("cp.async.cg.shared.global [%0], [%1], 16;" :: "r"(s), "l"(g));
}
__device__ __forceinline__ void cp_commit() {
    asm volatile("cp.async.commit_group;" ::: "memory");
}
__device__ __forceinline__ void cp_wait2() {
    asm volatile("cp.async.wait_group 2;" ::: "memory");
}
__device__ __forceinline__ void ldsm_x4(uint32_t (&r)[4], uint32_t addr) {
    asm volatile("ldmatrix.sync.aligned.m8n8.x4.shared.b16 {%0,%1,%2,%3}, [%4];"
                 : "=r"(r[0]), "=r"(r[1]), "=r"(r[2]), "=r"(r[3]) : "r"(addr));
}
__device__ __forceinline__ void ldsm_x2_t(uint32_t (&r)[2], uint32_t addr) {
    asm volatile("ldmatrix.sync.aligned.m8n8.x2.trans.shared.b16 {%0,%1}, [%2];"
                 : "=r"(r[0]), "=r"(r[1]) : "r"(addr));
}
__device__ __forceinline__ void mma_f16(float (&d)[4], const uint32_t (&a)[4],
                                        const uint32_t (&b)[2]) {
    asm volatile(
        "mma.sync.aligned.m16n8k16.row.col.f32.f16.f16.f32 "
        "{%0,%1,%2,%3}, {%4,%5,%6,%7}, {%8,%9}, {%0,%1,%2,%3};\n"
        : "+f"(d[0]), "+f"(d[1]), "+f"(d[2]), "+f"(d[3])
        : "r"(a[0]), "r"(a[1]), "r"(a[2]), "r"(a[3]), "r"(b[0]), "r"(b[1]));
}

// ---------------- tiling ----------------
#define BM   128
#define BN   256
#define BK   32            // fp16 k-depth per tile
#define NTHREADS 512
#define STAGES 4
#define A_ROW_B  80        // A smem row stride bytes, conflict-free ldmatrix
#define B_ROW_B  528       // B smem row stride bytes, conflict-free ldmatrix
#define A_ST_B   (BM * A_ROW_B)              // 10240
#define B_ST_B   (BK * B_ROW_B)              // 16896
#define STAGE_B  (A_ST_B + B_ST_B)           // 27136
#define SMEM_TOTAL (STAGES * STAGE_B)        // 108544
#define A_CHUNKS (BM * BK * 2 / 16)          // 512
#define B_CHUNKS (BK * BN * 2 / 16)          // 1024

// one stage of cp.async: 3 chunks/thread @ 512 threads
__device__ __forceinline__ void load_stage(uint32_t sbase, int st,
                                           const __half* __restrict__ Ag,
                                           const __half* __restrict__ Bg,
                                           int K, int Ntot, int tid) {
    const uint32_t sA = sbase + st * STAGE_B;
    const uint32_t sB = sA + A_ST_B;
#pragma unroll
    for (int j = 0; j < (A_CHUNKS + B_CHUNKS) / NTHREADS; j++) {
        const int c = tid + j * NTHREADS;
        if (c < A_CHUNKS) {
            const int row = c >> 2, q = c & 3;        // 4 chunks per A row
            cp16(sA + (uint32_t)(row * A_ROW_B + q * 16),
                 Ag + (size_t)row * K + q * 8);
        } else {
            const int b = c - A_CHUNKS;
            const int k = b >> 5, q = b & 31;         // 32 chunks per B row
            cp16(sB + (uint32_t)(k * B_ROW_B + q * 16),
                 Bg + (size_t)k * Ntot + q * 8);
        }
    }
}

// -------- GEMM: C[row,n] = sum_k A[row,k]*W[m,k,n] + bias[m,n] (fp16 in, fp32 out)
// 512 threads = 16 warps (2m x 8n), warp tile 64x32, ldmatrix + m16n8k16.
__launch_bounds__(NTHREADS, 1)
__global__ void gemm_f16(const __half* __restrict__ A,
                         const __half* __restrict__ W,
                         const float* __restrict__ bias,
                         float* __restrict__ C,
                         int K, int Ntot, int NT) {
    extern __shared__ __align__(16) char smc[];
    const uint32_t sbase = smem_u32(smc);

    const int tid  = threadIdx.x;
    const int lane = tid & 31;
    const int warp = tid >> 5;
    const int wm   = warp >> 3;      // 0..1
    const int wn   = warp & 7;       // 0..7
    const int g    = lane >> 2;      // 0..7
    const int r    = lane & 3;       // 0..3

    const int brow   = blockIdx.y * BM;
    const int bcol   = blockIdx.x * BN;
    const int member = brow >> 12;

    const __half* Ag0 = A + (size_t)brow * K;
    const __half* Bg0 = W + (size_t)member * K * Ntot + bcol;

    float acc[4][4][4];
#pragma unroll
    for (int i = 0; i < 4; i++)
#pragma unroll
        for (int j = 0; j < 4; j++)
#pragma unroll
            for (int c = 0; c < 4; c++) acc[i][j][c] = 0.f;

    // per-lane invariant pieces of ldmatrix addresses
    const uint32_t a_lane_off =
        (uint32_t)((lane & 15) * A_ROW_B + (lane >> 4) * 16);
    const uint32_t b_lane_off = (uint32_t)((lane & 15) * B_ROW_B);

#pragma unroll
    for (int s = 0; s < STAGES - 1; s++) {
        load_stage(sbase, s, Ag0 + s * BK, Bg0 + (size_t)s * BK * Ntot,
                   K, Ntot, tid);
        cp_commit();
    }

    for (int t = 0; t < NT; t++) {
        cp_wait2();
        __syncthreads();

        const int u = t + STAGES - 1;
        if (u < NT) {
            load_stage(sbase, u & (STAGES - 1), Ag0 + u * BK,
                       Bg0 + (size_t)u * BK * Ntot, K, Ntot, tid);
        }
        cp_commit();

        const uint32_t sA = sbase + (t & (STAGES - 1)) * STAGE_B;
        const uint32_t sB = sA + A_ST_B;

#pragma unroll
        for (int ks = 0; ks < 2; ks++) {
            uint32_t af[4][4];
            uint32_t bf[4][2];
#pragma unroll
            for (int mt = 0; mt < 4; mt++) {
                ldsm_x4(af[mt], sA + (uint32_t)((wm * 64 + mt * 16) * A_ROW_B +
                                                ks * 32) + a_lane_off);
            }
#pragma unroll
            for (int nt = 0; nt < 4; nt++) {
                ldsm_x2_t(bf[nt], sB + (uint32_t)(ks * 16 * B_ROW_B +
                                                  (wn * 32 + nt * 8) * 2) +
                                      b_lane_off);
            }
#pragma unroll
            for (int mt = 0; mt < 4; mt++)
#pragma unroll
                for (int nt = 0; nt < 4; nt++)
                    mma_f16(acc[mt][nt], af[mt], bf[nt]);
        }
    }

    // epilogue: bias + store fp32
    const float* bm = bias + (size_t)member * Ntot + bcol;
#pragma unroll
    for (int mt = 0; mt < 4; mt++) {
        const int row0 = brow + wm * 64 + mt * 16 + g;
#pragma unroll
        for (int nt = 0; nt < 4; nt++) {
            const int col0 = bcol + wn * 32 + nt * 8 + r * 2;
            const float bx0 = __ldg(bm + (col0 - bcol));
            const float bx1 = __ldg(bm + (col0 - bcol) + 1);
            float2 v0, v1;
            v0.x = acc[mt][nt][0] + bx0;
            v0.y = acc[mt][nt][1] + bx1;
            v1.x = acc[mt][nt][2] + bx0;
            v1.y = acc[mt][nt][3] + bx1;
            *(float2*)(C + (size_t)row0 * Ntot + col0) = v0;
            *(float2*)(C + (size_t)(row0 + 8) * Ntot + col0) = v1;
        }
    }
}

// ---------------- pre-pass: fp32 -> fp16 convert (8 elems/thread) ----------
__global__ void f32_to_f16(const float* __restrict__ in,
                           __half* __restrict__ out, int n8) {
    int i = blockIdx.x * blockDim.x + threadIdx.x;
    if (i >= n8) return;
    float4 a = ((const float4*)in)[2 * i];
    float4 b = ((const float4*)in)[2 * i + 1];
    __half2 h[4];
    h[0] = __floats2half2_rn(a.x, a.y);
    h[1] = __floats2half2_rn(a.z, a.w);
    h[2] = __floats2half2_rn(b.x, b.y);
    h[3] = __floats2half2_rn(b.z, b.w);
    ((uint4*)out)[i] = *(uint4*)h;
}

// ------------- fused LayerNorm + SiLU; fp32 in (g_h), fp16 out (g_hh) -------
__launch_bounds__(256)
__global__ void ln_silu_kernel(const float* __restrict__ ln_w,
                               const float* __restrict__ ln_b) {
    const int row = blockIdx.x;
    const int m   = row >> 12;
    const float* hp = g_h + (size_t)row * H_DIM;
    __half* op = g_hh + (size_t)row * H_DIM;
    const int t = threadIdx.x;

    float4 x = *(const float4*)(hp + t * 4);
    float s = x.x + x.y + x.z + x.w;
    float q = x.x * x.x + x.y * x.y + x.z * x.z + x.w * x.w;
#pragma unroll
    for (int o = 16; o; o >>= 1) {
        s += __shfl_xor_sync(0xffffffffu, s, o);
        q += __shfl_xor_sync(0xffffffffu, q, o);
    }
    __shared__ float rs[8], rq[8];
    if ((t & 31) == 0) { rs[t >> 5] = s; rq[t >> 5] = q; }
    __syncthreads();
    s = rs[0] + rs[1] + rs[2] + rs[3] + rs[4] + rs[5] + rs[6] + rs[7];
    q = rq[0] + rq[1] + rq[2] + rq[3] + rq[4] + rq[5] + rq[6] + rq[7];

    const float mu  = s * (1.0f / H_DIM);
    const float var = q * (1.0f / H_DIM) - mu * mu;
    const float inv = rsqrtf(var + 1e-5f);

    const float4 w = *(const float4*)(ln_w + (size_t)m * H_DIM + t * 4);
    const float4 b = *(const float4*)(ln_b + (size_t)m * H_DIM + t * 4);

    float y[4]; float v;
    v = (x.x - mu) * inv * w.x + b.x; y[0] = v / (1.f + __expf(-v));
    v = (x.y - mu) * inv * w.y + b.y; y[1] = v / (1.f + __expf(-v));
    v = (x.z - mu) * inv * w.z + b.z; y[2] = v / (1.f + __expf(-v));
    v = (x.w - mu) * inv * w.w + b.w; y[3] = v / (1.f + __expf(-v));
    __half2 h2[2];
    h2[0] = __floats2half2_rn(y[0], y[1]);
    h2[1] = __floats2half2_rn(y[2], y[3]);
    *(uint2*)(op + t * 4) = *(uint2*)h2;
}

// ---------------- launch ----------------
extern "C" void kernel_launch(void* const* d_in, const int* in_sizes, int n_in,
                              void* d_out, int out_size) {
    const float* x  = (const float*)d_in[0];
    const float* W1 = (const float*)d_in[1];
    const float* b1 = (const float*)d_in[2];
    const float* lw = (const float*)d_in[3];
    const float* lb = (const float*)d_in[4];
    const float* W2 = (const float*)d_in[5];
    const float* b2 = (const float*)d_in[6];
    float* out = (float*)d_out;

    __half *xh, *w1h, *w2h, *hh;
    float* h;
    cudaGetSymbolAddress((void**)&xh,  g_xh);
    cudaGetSymbolAddress((void**)&w1h, g_w1h);
    cudaGetSymbolAddress((void**)&w2h, g_w2h);
    cudaGetSymbolAddress((void**)&h,   g_h);
    cudaGetSymbolAddress((void**)&hh,  g_hh);

    cudaFuncSetAttribute(gemm_f16, cudaFuncAttributeMaxDynamicSharedMemorySize,
                         SMEM_TOTAL);

    // pre-pass: fp32 -> fp16
    f32_to_f16<<<(ROWS * E_DIM / 8 + 255) / 256, 256>>>(x, xh,
                                                        ROWS * E_DIM / 8);
    f32_to_f16<<<(MEMB * E_DIM * H_DIM / 8 + 255) / 256, 256>>>(
        W1, w1h, MEMB * E_DIM * H_DIM / 8);
    f32_to_f16<<<(MEMB * H_DIM * V_DIM / 8 + 255) / 256, 256>>>(
        W2, w2h, MEMB * H_DIM * V_DIM / 8);

    // GEMM1: [32768,512] x [8: 512->1024] -> h (+b1), fp32 out
    gemm_f16<<<dim3(H_DIM / BN, ROWS / BM), NTHREADS, SMEM_TOTAL>>>(
        xh, w1h, b1, h, E_DIM, H_DIM, E_DIM / BK);
    // LayerNorm + SiLU, fp16 out
    ln_silu_kernel<<<ROWS, 256>>>(lw, lb);
    // GEMM2: [32768,1024] x [8: 1024->4096] -> out (+b2)
    gemm_f16<<<dim3(V_DIM / BN, ROWS / BM), NTHREADS, SMEM_TOTAL>>>(
        hh, w2h, b2, out, H_DIM, V_DIM, H_DIM / BK);
}

// round 7
// speedup vs baseline: 2.0384x; 1.0979x over previous
#include <cuda_runtime.h>
#include <cuda_fp16.h>
#include <cstdint>
#include <cstddef>

#define MEMB   8
#define BATCHI 4096
#define E_DIM  512
#define H_DIM  1024
#define V_DIM  4096
#define ROWS   (MEMB * BATCHI)   // 32768

// ---------------- scratch (device globals: allocation-free) ----------------
__device__ __half g_xh [(size_t)ROWS * E_DIM];          // fp16 x
__device__ __half g_w1h[(size_t)MEMB * E_DIM * H_DIM];  // fp16 W1
__device__ __half g_w2h[(size_t)MEMB * H_DIM * V_DIM];  // fp16 W2
__device__ float  g_h  [(size_t)ROWS * H_DIM];          // fp32 hidden (GEMM1 out)
__device__ __half g_hh [(size_t)ROWS * H_DIM];          // fp16 hidden (GEMM2 in)

// ---------------- helpers ----------------
__device__ __forceinline__ uint32_t smem_u32(const void* p) {
    uint32_t a;
    asm("{ .reg .u64 t; cvta.to.shared.u64 t, %1; cvt.u32.u64 %0, t; }"
        : "=r"(a) : "l"(p));
    return a;
}
__device__ __forceinline__ void cp16(uint32_t s, const void* g) {
    asm volatile("cp.async.cg.shared.global [%0], [%1], 16;" :: "r"(s), "l"(g));
}
__device__ __forceinline__ void cp_commit() {
    asm volatile("cp.async.commit_group;" ::: "memory");
}
__device__ __forceinline__ void cp_wait2() {
    asm volatile("cp.async.wait_group 2;" ::: "memory");
}
__device__ __forceinline__ void ldsm_x4(uint32_t (&r)[4], uint32_t addr) {
    asm volatile("ldmatrix.sync.aligned.m8n8.x4.shared.b16 {%0,%1,%2,%3}, [%4];"
                 : "=r"(r[0]), "=r"(r[1]), "=r"(r[2]), "=r"(r[3]) : "r"(addr));
}
__device__ __forceinline__ void ldsm_x2_t(uint32_t (&r)[2], uint32_t addr) {
    asm volatile("ldmatrix.sync.aligned.m8n8.x2.trans.shared.b16 {%0,%1}, [%2];"
                 : "=r"(r[0]), "=r"(r[1]) : "r"(addr));
}
__device__ __forceinline__ void mma_f16(float (&d)[4], const uint32_t (&a)[4],
                                        const uint32_t (&b)[2]) {
    asm volatile(
        "mma.sync.aligned.m16n8k16.row.col.f32.f16.f16.f32 "
        "{%0,%1,%2,%3}, {%4,%5,%6,%7}, {%8,%9}, {%0,%1,%2,%3};\n"
        : "+f"(d[0]), "+f"(d[1]), "+f"(d[2]), "+f"(d[3])
        : "r"(a[0]), "r"(a[1]), "r"(a[2]), "r"(a[3]), "r"(b[0]), "r"(b[1]));
}

// ---------------- tiling ----------------
#define BM   128
#define BN   128
#define BK   32            // fp16 k-depth per tile
#define NTHREADS 256
#define STAGES 4
#define A_ROW_B  80        // A smem row stride bytes, conflict-free ldmatrix
#define B_ROW_B  272       // B smem row stride bytes (128 halfs + pad)
#define A_ST_B   (BM * A_ROW_B)              // 10240
#define B_ST_B   (BK * B_ROW_B)              // 8704
#define STAGE_B  (A_ST_B + B_ST_B)           // 18944
#define SMEM_TOTAL (STAGES * STAGE_B)        // 75776 (x2 CTA = 151552)
#define A_CHUNKS (BM * BK * 2 / 16)          // 512
#define B_CHUNKS (BK * BN * 2 / 16)          // 512

// one stage of cp.async: 4 chunks/thread @ 256 threads
__device__ __forceinline__ void load_stage(uint32_t sbase, int st,
                                           const __half* __restrict__ Ag,
                                           const __half* __restrict__ Bg,
                                           int K, int Ntot, int tid) {
    const uint32_t sA = sbase + st * STAGE_B;
    const uint32_t sB = sA + A_ST_B;
#pragma unroll
    for (int j = 0; j < (A_CHUNKS + B_CHUNKS) / NTHREADS; j++) {
        const int c = tid + j * NTHREADS;
        if (c < A_CHUNKS) {
            const int row = c >> 2, q = c & 3;        // 4 chunks per A row
            cp16(sA + (uint32_t)(row * A_ROW_B + q * 16),
                 Ag + (size_t)row * K + q * 8);
        } else {
            const int b = c - A_CHUNKS;
            const int k = b >> 4, q = b & 15;         // 16 chunks per B row
            cp16(sB + (uint32_t)(k * B_ROW_B + q * 16),
                 Bg + (size_t)k * Ntot + q * 8);
        }
    }
}

// -------- GEMM: C[row,n] = sum_k A[row,k]*W[m,k,n] + bias[m,n] (fp16 in, fp32 out)
// 256 threads = 8 warps (2m x 4n), warp tile 64x32, 2 CTAs/SM for bubble overlap.
__launch_bounds__(NTHREADS, 2)
__global__ void gemm_f16(const __half* __restrict__ A,
                         const __half* __restrict__ W,
                         const float* __restrict__ bias,
                         float* __restrict__ C,
                         int K, int Ntot, int NT) {
    extern __shared__ __align__(16) char smc[];
    const uint32_t sbase = smem_u32(smc);

    const int tid  = threadIdx.x;
    const int lane = tid & 31;
    const int warp = tid >> 5;
    const int wm   = warp >> 2;      // 0..1
    const int wn   = warp & 3;       // 0..3
    const int g    = lane >> 2;      // 0..7
    const int r    = lane & 3;       // 0..3

    const int brow   = blockIdx.y * BM;
    const int bcol   = blockIdx.x * BN;
    const int member = brow >> 12;

    const __half* Ag0 = A + (size_t)brow * K;
    const __half* Bg0 = W + (size_t)member * K * Ntot + bcol;

    float acc[4][4][4];
#pragma unroll
    for (int i = 0; i < 4; i++)
#pragma unroll
        for (int j = 0; j < 4; j++)
#pragma unroll
            for (int c = 0; c < 4; c++) acc[i][j][c] = 0.f;

    // per-lane invariant pieces of ldmatrix addresses
    const uint32_t a_lane_off =
        (uint32_t)((lane & 15) * A_ROW_B + (lane >> 4) * 16);
    const uint32_t b_lane_off = (uint32_t)((lane & 15) * B_ROW_B);

#pragma unroll
    for (int s = 0; s < STAGES - 1; s++) {
        load_stage(sbase, s, Ag0 + s * BK, Bg0 + (size_t)s * BK * Ntot,
                   K, Ntot, tid);
        cp_commit();
    }

    for (int t = 0; t < NT; t++) {
        cp_wait2();
        __syncthreads();

        const int u = t + STAGES - 1;
        if (u < NT) {
            load_stage(sbase, u & (STAGES - 1), Ag0 + u * BK,
                       Bg0 + (size_t)u * BK * Ntot, K, Ntot, tid);
        }
        cp_commit();

        const uint32_t sA = sbase + (t & (STAGES - 1)) * STAGE_B;
        const uint32_t sB = sA + A_ST_B;

#pragma unroll
        for (int ks = 0; ks < 2; ks++) {
            uint32_t af[4][4];
            uint32_t bf[4][2];
#pragma unroll
            for (int mt = 0; mt < 4; mt++) {
                ldsm_x4(af[mt], sA + (uint32_t)((wm * 64 + mt * 16) * A_ROW_B +
                                                ks * 32) + a_lane_off);
            }
#pragma unroll
            for (int nt = 0; nt < 4; nt++) {
                ldsm_x2_t(bf[nt], sB + (uint32_t)(ks * 16 * B_ROW_B +
                                                  (wn * 32 + nt * 8) * 2) +
                                      b_lane_off);
            }
#pragma unroll
            for (int mt = 0; mt < 4; mt++)
#pragma unroll
                for (int nt = 0; nt < 4; nt++)
                    mma_f16(acc[mt][nt], af[mt], bf[nt]);
        }
    }

    // epilogue: bias + store fp32
    const float* bm = bias + (size_t)member * Ntot + bcol;
#pragma unroll
    for (int mt = 0; mt < 4; mt++) {
        const int row0 = brow + wm * 64 + mt * 16 + g;
#pragma unroll
        for (int nt = 0; nt < 4; nt++) {
            const int col0 = bcol + wn * 32 + nt * 8 + r * 2;
            const float bx0 = __ldg(bm + (col0 - bcol));
            const float bx1 = __ldg(bm + (col0 - bcol) + 1);
            float2 v0, v1;
            v0.x = acc[mt][nt][0] + bx0;
            v0.y = acc[mt][nt][1] + bx1;
            v1.x = acc[mt][nt][2] + bx0;
            v1.y = acc[mt][nt][3] + bx1;
            *(float2*)(C + (size_t)row0 * Ntot + col0) = v0;
            *(float2*)(C + (size_t)(row0 + 8) * Ntot + col0) = v1;
        }
    }
}

// ---------------- pre-pass: fp32 -> fp16 convert (8 elems/thread) ----------
__global__ void f32_to_f16(const float* __restrict__ in,
                           __half* __restrict__ out, int n8) {
    int i = blockIdx.x * blockDim.x + threadIdx.x;
    if (i >= n8) return;
    float4 a = ((const float4*)in)[2 * i];
    float4 b = ((const float4*)in)[2 * i + 1];
    __half2 h[4];
    h[0] = __floats2half2_rn(a.x, a.y);
    h[1] = __floats2half2_rn(a.z, a.w);
    h[2] = __floats2half2_rn(b.x, b.y);
    h[3] = __floats2half2_rn(b.z, b.w);
    ((uint4*)out)[i] = *(uint4*)h;
}

// ------------- fused LayerNorm + SiLU; fp32 in (g_h), fp16 out (g_hh) -------
__launch_bounds__(256)
__global__ void ln_silu_kernel(const float* __restrict__ ln_w,
                               const float* __restrict__ ln_b) {
    const int row = blockIdx.x;
    const int m   = row >> 12;
    const float* hp = g_h + (size_t)row * H_DIM;
    __half* op = g_hh + (size_t)row * H_DIM;
    const int t = threadIdx.x;

    float4 x = *(const float4*)(hp + t * 4);
    float s = x.x + x.y + x.z + x.w;
    float q = x.x * x.x + x.y * x.y + x.z * x.z + x.w * x.w;
#pragma unroll
    for (int o = 16; o; o >>= 1) {
        s += __shfl_xor_sync(0xffffffffu, s, o);
        q += __shfl_xor_sync(0xffffffffu, q, o);
    }
    __shared__ float rs[8], rq[8];
    if ((t & 31) == 0) { rs[t >> 5] = s; rq[t >> 5] = q; }
    __syncthreads();
    s = rs[0] + rs[1] + rs[2] + rs[3] + rs[4] + rs[5] + rs[6] + rs[7];
    q = rq[0] + rq[1] + rq[2] + rq[3] + rq[4] + rq[5] + rq[6] + rq[7];

    const float mu  = s * (1.0f / H_DIM);
    const float var = q * (1.0f / H_DIM) - mu * mu;
    const float inv = rsqrtf(var + 1e-5f);

    const float4 w = *(const float4*)(ln_w + (size_t)m * H_DIM + t * 4);
    const float4 b = *(const float4*)(ln_b + (size_t)m * H_DIM + t * 4);

    float y[4]; float v;
    v = (x.x - mu) * inv * w.x + b.x; y[0] = v / (1.f + __expf(-v));
    v = (x.y - mu) * inv * w.y + b.y; y[1] = v / (1.f + __expf(-v));
    v = (x.z - mu) * inv * w.z + b.z; y[2] = v / (1.f + __expf(-v));
    v = (x.w - mu) * inv * w.w + b.w; y[3] = v / (1.f + __expf(-v));
    __half2 h2[2];
    h2[0] = __floats2half2_rn(y[0], y[1]);
    h2[1] = __floats2half2_rn(y[2], y[3]);
    *(uint2*)(op + t * 4) = *(uint2*)h2;
}

// ---------------- launch ----------------
extern "C" void kernel_launch(void* const* d_in, const int* in_sizes, int n_in,
                              void* d_out, int out_size) {
    const float* x  = (const float*)d_in[0];
    const float* W1 = (const float*)d_in[1];
    const float* b1 = (const float*)d_in[2];
    const float* lw = (const float*)d_in[3];
    const float* lb = (const float*)d_in[4];
    const float* W2 = (const float*)d_in[5];
    const float* b2 = (const float*)d_in[6];
    float* out = (float*)d_out;

    __half *xh, *w1h, *w2h, *hh;
    float* h;
    cudaGetSymbolAddress((void**)&xh,  g_xh);
    cudaGetSymbolAddress((void**)&w1h, g_w1h);
    cudaGetSymbolAddress((void**)&w2h, g_w2h);
    cudaGetSymbolAddress((void**)&h,   g_h);
    cudaGetSymbolAddress((void**)&hh,  g_hh);

    cudaFuncSetAttribute(gemm_f16, cudaFuncAttributeMaxDynamicSharedMemorySize,
                         SMEM_TOTAL);

    // pre-pass: fp32 -> fp16
    f32_to_f16<<<(ROWS * E_DIM / 8 + 255) / 256, 256>>>(x, xh,
                                                        ROWS * E_DIM / 8);
    f32_to_f16<<<(MEMB * E_DIM * H_DIM / 8 + 255) / 256, 256>>>(
        W1, w1h, MEMB * E_DIM * H_DIM / 8);
    f32_to_f16<<<(MEMB * H_DIM * V_DIM / 8 + 255) / 256, 256>>>(
        W2, w2h, MEMB * H_DIM * V_DIM / 8);

    // GEMM1: [32768,512] x [8: 512->1024] -> h (+b1), fp32 out
    gemm_f16<<<dim3(H_DIM / BN, ROWS / BM), NTHREADS, SMEM_TOTAL>>>(
        xh, w1h, b1, h, E_DIM, H_DIM, E_DIM / BK);
    // LayerNorm + SiLU, fp16 out
    ln_silu_kernel<<<ROWS, 256>>>(lw, lb);
    // GEMM2: [32768,1024] x [8: 1024->4096] -> out (+b2)
    gemm_f16<<<dim3(V_DIM / BN, ROWS / BM), NTHREADS, SMEM_TOTAL>>>(
        hh, w2h, b2, out, H_DIM, V_DIM, H_DIM / BK);
}

// round 8
// speedup vs baseline: 2.1804x; 1.0697x over previous
#include <cuda_runtime.h>
#include <cuda_fp16.h>
#include <cstdint>
#include <cstddef>

#define MEMB   8
#define BATCHI 4096
#define E_DIM  512
#define H_DIM  1024
#define V_DIM  4096
#define ROWS   (MEMB * BATCHI)   // 32768

// ---------------- scratch (device globals: allocation-free) ----------------
__device__ __half g_xh [(size_t)ROWS * E_DIM];          // fp16 x
__device__ __half g_w1h[(size_t)MEMB * E_DIM * H_DIM];  // fp16 W1
__device__ __half g_w2h[(size_t)MEMB * H_DIM * V_DIM];  // fp16 W2
__device__ float  g_h  [(size_t)ROWS * H_DIM];          // fp32 hidden (GEMM1 out)
__device__ __half g_hh [(size_t)ROWS * H_DIM];          // fp16 hidden (GEMM2 in)

// ---------------- helpers ----------------
__device__ __forceinline__ uint32_t smem_u32(const void* p) {
    uint32_t a;
    asm("{ .reg .u64 t; cvta.to.shared.u64 t, %1; cvt.u32.u64 %0, t; }"
        : "=r"(a) : "l"(p));
    return a;
}
__device__ __forceinline__ void cp16(uint32_t s, const void* g) {
    asm volatile("cp.async.cg.shared.global [%0], [%1], 16;" :: "r"(s), "l"(g));
}
__device__ __forceinline__ void cp_commit() {
    asm volatile("cp.async.commit_group;" ::: "memory");
}
__device__ __forceinline__ void cp_wait2() {
    asm volatile("cp.async.wait_group 2;" ::: "memory");
}
__device__ __forceinline__ void ldsm_x4(uint32_t (&r)[4], uint32_t addr) {
    asm volatile("ldmatrix.sync.aligned.m8n8.x4.shared.b16 {%0,%1,%2,%3}, [%4];"
                 : "=r"(r[0]), "=r"(r[1]), "=r"(r[2]), "=r"(r[3]) : "r"(addr));
}
__device__ __forceinline__ void ldsm_x2_t(uint32_t (&r)[2], uint32_t addr) {
    asm volatile("ldmatrix.sync.aligned.m8n8.x2.trans.shared.b16 {%0,%1}, [%2];"
                 : "=r"(r[0]), "=r"(r[1]) : "r"(addr));
}
__device__ __forceinline__ void mma_f16(float (&d)[4], const uint32_t (&a)[4],
                                        const uint32_t (&b)[2]) {
    asm volatile(
        "mma.sync.aligned.m16n8k16.row.col.f32.f16.f16.f32 "
        "{%0,%1,%2,%3}, {%4,%5,%6,%7}, {%8,%9}, {%0,%1,%2,%3};\n"
        : "+f"(d[0]), "+f"(d[1]), "+f"(d[2]), "+f"(d[3])
        : "r"(a[0]), "r"(a[1]), "r"(a[2]), "r"(a[3]), "r"(b[0]), "r"(b[1]));
}

// ---------------- tiling ----------------
#define BM   128
#define BN   128
#define BK   32            // fp16 k-depth per tile
#define NTHREADS 128       // 4 warps (2m x 2n), warp tile 64x64
#define STAGES 4
#define A_ROW_B  80        // A smem row stride bytes, conflict-free ldmatrix
#define B_ROW_B  272       // B smem row stride bytes (128 halfs + pad)
#define A_ST_B   (BM * A_ROW_B)              // 10240
#define B_ST_B   (BK * B_ROW_B)              // 8704
#define STAGE_B  (A_ST_B + B_ST_B)           // 18944
#define SMEM_TOTAL (STAGES * STAGE_B)        // 75776 (x2 CTA = 151552)
#define A_CHUNKS (BM * BK * 2 / 16)          // 512
#define B_CHUNKS (BK * BN * 2 / 16)          // 512

// one stage of cp.async: 8 chunks/thread @ 128 threads
__device__ __forceinline__ void load_stage(uint32_t sbase, int st,
                                           const __half* __restrict__ Ag,
                                           const __half* __restrict__ Bg,
                                           int K, int Ntot, int tid) {
    const uint32_t sA = sbase + st * STAGE_B;
    const uint32_t sB = sA + A_ST_B;
#pragma unroll
    for (int j = 0; j < (A_CHUNKS + B_CHUNKS) / NTHREADS; j++) {
        const int c = tid + j * NTHREADS;
        if (c < A_CHUNKS) {
            const int row = c >> 2, q = c & 3;        // 4 chunks per A row
            cp16(sA + (uint32_t)(row * A_ROW_B + q * 16),
                 Ag + (size_t)row * K + q * 8);
        } else {
            const int b = c - A_CHUNKS;
            const int k = b >> 4, q = b & 15;         // 16 chunks per B row
            cp16(sB + (uint32_t)(k * B_ROW_B + q * 16),
                 Bg + (size_t)k * Ntot + q * 8);
        }
    }
}

// -------- GEMM: C[row,n] = sum_k A[row,k]*W[m,k,n] + bias[m,n] (fp16 in, fp32 out)
// 128 threads = 4 warps (2m x 2n), warp tile 64x64, 2 CTAs/SM.
__launch_bounds__(NTHREADS, 2)
__global__ void gemm_f16(const __half* __restrict__ A,
                         const __half* __restrict__ W,
                         const float* __restrict__ bias,
                         float* __restrict__ C,
                         int K, int Ntot, int NT) {
    extern __shared__ __align__(16) char smc[];
    const uint32_t sbase = smem_u32(smc);

    const int tid  = threadIdx.x;
    const int lane = tid & 31;
    const int warp = tid >> 5;
    const int wm   = warp >> 1;      // 0..1
    const int wn   = warp & 1;       // 0..1
    const int g    = lane >> 2;      // 0..7
    const int r    = lane & 3;       // 0..3

    const int brow   = blockIdx.y * BM;
    const int bcol   = blockIdx.x * BN;
    const int member = brow >> 12;

    const __half* Ag0 = A + (size_t)brow * K;
    const __half* Bg0 = W + (size_t)member * K * Ntot + bcol;

    float acc[4][8][4];
#pragma unroll
    for (int i = 0; i < 4; i++)
#pragma unroll
        for (int j = 0; j < 8; j++)
#pragma unroll
            for (int c = 0; c < 4; c++) acc[i][j][c] = 0.f;

    // per-lane invariant pieces of ldmatrix addresses
    const uint32_t a_lane_off =
        (uint32_t)((lane & 15) * A_ROW_B + (lane >> 4) * 16);
    const uint32_t b_lane_off = (uint32_t)((lane & 15) * B_ROW_B);

#pragma unroll
    for (int s = 0; s < STAGES - 1; s++) {
        load_stage(sbase, s, Ag0 + s * BK, Bg0 + (size_t)s * BK * Ntot,
                   K, Ntot, tid);
        cp_commit();
    }

    for (int t = 0; t < NT; t++) {
        cp_wait2();
        __syncthreads();

        const int u = t + STAGES - 1;
        if (u < NT) {
            load_stage(sbase, u & (STAGES - 1), Ag0 + u * BK,
                       Bg0 + (size_t)u * BK * Ntot, K, Ntot, tid);
        }
        cp_commit();

        const uint32_t sA = sbase + (t & (STAGES - 1)) * STAGE_B;
        const uint32_t sB = sA + A_ST_B;

#pragma unroll
        for (int ks = 0; ks < 2; ks++) {
            uint32_t af[4][4];
            uint32_t bf[8][2];
#pragma unroll
            for (int mt = 0; mt < 4; mt++) {
                ldsm_x4(af[mt], sA + (uint32_t)((wm * 64 + mt * 16) * A_ROW_B +
                                                ks * 32) + a_lane_off);
            }
#pragma unroll
            for (int nt = 0; nt < 8; nt++) {
                ldsm_x2_t(bf[nt], sB + (uint32_t)(ks * 16 * B_ROW_B +
                                                  (wn * 64 + nt * 8) * 2) +
                                      b_lane_off);
            }
#pragma unroll
            for (int mt = 0; mt < 4; mt++)
#pragma unroll
                for (int nt = 0; nt < 8; nt++)
                    mma_f16(acc[mt][nt], af[mt], bf[nt]);
        }
    }

    // epilogue: bias + store fp32
    const float* bm = bias + (size_t)member * Ntot + bcol;
#pragma unroll
    for (int mt = 0; mt < 4; mt++) {
        const int row0 = brow + wm * 64 + mt * 16 + g;
#pragma unroll
        for (int nt = 0; nt < 8; nt++) {
            const int col0 = bcol + wn * 64 + nt * 8 + r * 2;
            const float bx0 = __ldg(bm + (col0 - bcol));
            const float bx1 = __ldg(bm + (col0 - bcol) + 1);
            float2 v0, v1;
            v0.x = acc[mt][nt][0] + bx0;
            v0.y = acc[mt][nt][1] + bx1;
            v1.x = acc[mt][nt][2] + bx0;
            v1.y = acc[mt][nt][3] + bx1;
            *(float2*)(C + (size_t)row0 * Ntot + col0) = v0;
            *(float2*)(C + (size_t)(row0 + 8) * Ntot + col0) = v1;
        }
    }
}

// ---------------- pre-pass: fp32 -> fp16 convert (8 elems/thread) ----------
__global__ void f32_to_f16(const float* __restrict__ in,
                           __half* __restrict__ out, int n8) {
    int i = blockIdx.x * blockDim.x + threadIdx.x;
    if (i >= n8) return;
    float4 a = ((const float4*)in)[2 * i];
    float4 b = ((const float4*)in)[2 * i + 1];
    __half2 h[4];
    h[0] = __floats2half2_rn(a.x, a.y);
    h[1] = __floats2half2_rn(a.z, a.w);
    h[2] = __floats2half2_rn(b.x, b.y);
    h[3] = __floats2half2_rn(b.z, b.w);
    ((uint4*)out)[i] = *(uint4*)h;
}

// ------------- fused LayerNorm + SiLU; fp32 in (g_h), fp16 out (g_hh) -------
__launch_bounds__(256)
__global__ void ln_silu_kernel(const float* __restrict__ ln_w,
                               const float* __restrict__ ln_b) {
    const int row = blockIdx.x;
    const int m   = row >> 12;
    const float* hp = g_h + (size_t)row * H_DIM;
    __half* op = g_hh + (size_t)row * H_DIM;
    const int t = threadIdx.x;

    float4 x = *(const float4*)(hp + t * 4);
    float s = x.x + x.y + x.z + x.w;
    float q = x.x * x.x + x.y * x.y + x.z * x.z + x.w * x.w;
#pragma unroll
    for (int o = 16; o; o >>= 1) {
        s += __shfl_xor_sync(0xffffffffu, s, o);
        q += __shfl_xor_sync(0xffffffffu, q, o);
    }
    __shared__ float rs[8], rq[8];
    if ((t & 31) == 0) { rs[t >> 5] = s; rq[t >> 5] = q; }
    __syncthreads();
    s = rs[0] + rs[1] + rs[2] + rs[3] + rs[4] + rs[5] + rs[6] + rs[7];
    q = rq[0] + rq[1] + rq[2] + rq[3] + rq[4] + rq[5] + rq[6] + rq[7];

    const float mu  = s * (1.0f / H_DIM);
    const float var = q * (1.0f / H_DIM) - mu * mu;
    const float inv = rsqrtf(var + 1e-5f);

    const float4 w = *(const float4*)(ln_w + (size_t)m * H_DIM + t * 4);
    const float4 b = *(const float4*)(ln_b + (size_t)m * H_DIM + t * 4);

    float y[4]; float v;
    v = (x.x - mu) * inv * w.x + b.x; y[0] = v / (1.f + __expf(-v));
    v = (x.y - mu) * inv * w.y + b.y; y[1] = v / (1.f + __expf(-v));
    v = (x.z - mu) * inv * w.z + b.z; y[2] = v / (1.f + __expf(-v));
    v = (x.w - mu) * inv * w.w + b.w; y[3] = v / (1.f + __expf(-v));
    __half2 h2[2];
    h2[0] = __floats2half2_rn(y[0], y[1]);
    h2[1] = __floats2half2_rn(y[2], y[3]);
    *(uint2*)(op + t * 4) = *(uint2*)h2;
}

// ---------------- launch ----------------
extern "C" void kernel_launch(void* const* d_in, const int* in_sizes, int n_in,
                              void* d_out, int out_size) {
    const float* x  = (const float*)d_in[0];
    const float* W1 = (const float*)d_in[1];
    const float* b1 = (const float*)d_in[2];
    const float* lw = (const float*)d_in[3];
    const float* lb = (const float*)d_in[4];
    const float* W2 = (const float*)d_in[5];
    const float* b2 = (const float*)d_in[6];
    float* out = (float*)d_out;

    __half *xh, *w1h, *w2h, *hh;
    float* h;
    cudaGetSymbolAddress((void**)&xh,  g_xh);
    cudaGetSymbolAddress((void**)&w1h, g_w1h);
    cudaGetSymbolAddress((void**)&w2h, g_w2h);
    cudaGetSymbolAddress((void**)&h,   g_h);
    cudaGetSymbolAddress((void**)&hh,  g_hh);

    cudaFuncSetAttribute(gemm_f16, cudaFuncAttributeMaxDynamicSharedMemorySize,
                         SMEM_TOTAL);

    // pre-pass: fp32 -> fp16
    f32_to_f16<<<(ROWS * E_DIM / 8 + 255) / 256, 256>>>(x, xh,
                                                        ROWS * E_DIM / 8);
    f32_to_f16<<<(MEMB * E_DIM * H_DIM / 8 + 255) / 256, 256>>>(
        W1, w1h, MEMB * E_DIM * H_DIM / 8);
    f32_to_f16<<<(MEMB * H_DIM * V_DIM / 8 + 255) / 256, 256>>>(
        W2, w2h, MEMB * H_DIM * V_DIM / 8);

    // GEMM1: [32768,512] x [8: 512->1024] -> h (+b1), fp32 out
    gemm_f16<<<dim3(H_DIM / BN, ROWS / BM), NTHREADS, SMEM_TOTAL>>>(
        xh, w1h, b1, h, E_DIM, H_DIM, E_DIM / BK);
    // LayerNorm + SiLU, fp16 out
    ln_silu_kernel<<<ROWS, 256>>>(lw, lb);
    // GEMM2: [32768,1024] x [8: 1024->4096] -> out (+b2)
    gemm_f16<<<dim3(V_DIM / BN, ROWS / BM), NTHREADS, SMEM_TOTAL>>>(
        hh, w2h, b2, out, H_DIM, V_DIM, H_DIM / BK);
}

// round 9
// speedup vs baseline: 2.2625x; 1.0377x over previous
#include <cuda_runtime.h>
#include <cuda_fp16.h>
#include <cstdint>
#include <cstddef>

#define MEMB   8
#define BATCHI 4096
#define E_DIM  512
#define H_DIM  1024
#define V_DIM  4096
#define ROWS   (MEMB * BATCHI)   // 32768

// ---------------- scratch (device globals: allocation-free) ----------------
__device__ __half g_xh [(size_t)ROWS * E_DIM];          // fp16 x
__device__ __half g_w1h[(size_t)MEMB * E_DIM * H_DIM];  // fp16 W1
__device__ __half g_w2h[(size_t)MEMB * H_DIM * V_DIM];  // fp16 W2
__device__ float  g_h  [(size_t)ROWS * H_DIM];          // fp32 hidden (GEMM1 out)
__device__ __half g_hh [(size_t)ROWS * H_DIM];          // fp16 hidden (GEMM2 in)

// ---------------- helpers ----------------
__device__ __forceinline__ uint32_t smem_u32(const void* p) {
    uint32_t a;
    asm("{ .reg .u64 t; cvta.to.shared.u64 t, %1; cvt.u32.u64 %0, t; }"
        : "=r"(a) : "l"(p));
    return a;
}
__device__ __forceinline__ void cp16(uint32_t s, const void* g) {
    asm volatile("cp.async.cg.shared.global [%0], [%1], 16;" :: "r"(s), "l"(g));
}
__device__ __forceinline__ void cp_commit() {
    asm volatile("cp.async.commit_group;" ::: "memory");
}
__device__ __forceinline__ void cp_wait1() {
    asm volatile("cp.async.wait_group 1;" ::: "memory");
}
__device__ __forceinline__ void ldsm_x4(uint32_t (&r)[4], uint32_t addr) {
    asm volatile("ldmatrix.sync.aligned.m8n8.x4.shared.b16 {%0,%1,%2,%3}, [%4];"
                 : "=r"(r[0]), "=r"(r[1]), "=r"(r[2]), "=r"(r[3]) : "r"(addr));
}
__device__ __forceinline__ void ldsm_x2_t(uint32_t (&r)[2], uint32_t addr) {
    asm volatile("ldmatrix.sync.aligned.m8n8.x2.trans.shared.b16 {%0,%1}, [%2];"
                 : "=r"(r[0]), "=r"(r[1]) : "r"(addr));
}
__device__ __forceinline__ void mma_f16(float (&d)[4], const uint32_t (&a)[4],
                                        const uint32_t (&b)[2]) {
    asm volatile(
        "mma.sync.aligned.m16n8k16.row.col.f32.f16.f16.f32 "
        "{%0,%1,%2,%3}, {%4,%5,%6,%7}, {%8,%9}, {%0,%1,%2,%3};\n"
        : "+f"(d[0]), "+f"(d[1]), "+f"(d[2]), "+f"(d[3])
        : "r"(a[0]), "r"(a[1]), "r"(a[2]), "r"(a[3]), "r"(b[0]), "r"(b[1]));
}

// ---------------- tiling ----------------
#define BM   128
#define BN   128
#define BK   64            // fp16 k-depth per tile (4 ks steps of 16)
#define NTHREADS 128       // 4 warps (2m x 2n), warp tile 64x64
#define STAGES 3
#define A_ROW_B  144       // 64 halfs (128B) + 16B pad, conflict-free ldmatrix
#define B_ROW_B  272       // 128 halfs (256B) + 16B pad, conflict-free ldmatrix
#define A_ST_B   (BM * A_ROW_B)              // 18432
#define B_ST_B   (BK * B_ROW_B)              // 17408
#define STAGE_B  (A_ST_B + B_ST_B)           // 35840
#define SMEM_TOTAL (STAGES * STAGE_B)        // 107520 (x2 CTA = 215040)
#define A_CHUNKS (BM * BK * 2 / 16)          // 1024
#define B_CHUNKS (BK * BN * 2 / 16)          // 1024

// one stage of cp.async: 16 chunks/thread @ 128 threads
__device__ __forceinline__ void load_stage(uint32_t sbase, int st,
                                           const __half* __restrict__ Ag,
                                           const __half* __restrict__ Bg,
                                           int K, int Ntot, int tid) {
    const uint32_t sA = sbase + st * STAGE_B;
    const uint32_t sB = sA + A_ST_B;
#pragma unroll
    for (int j = 0; j < (A_CHUNKS + B_CHUNKS) / NTHREADS; j++) {
        const int c = tid + j * NTHREADS;
        if (c < A_CHUNKS) {
            const int row = c >> 3, q = c & 7;        // 8 chunks per A row
            cp16(sA + (uint32_t)(row * A_ROW_B + q * 16),
                 Ag + (size_t)row * K + q * 8);
        } else {
            const int b = c - A_CHUNKS;
            const int k = b >> 4, q = b & 15;         // 16 chunks per B row
            cp16(sB + (uint32_t)(k * B_ROW_B + q * 16),
                 Bg + (size_t)k * Ntot + q * 8);
        }
    }
}

// load one ks-step's fragments (warp tile 64x64)
__device__ __forceinline__ void frag_load(uint32_t (&af)[4][4], uint32_t (&bf)[8][2],
                                          uint32_t sA, uint32_t sB, int ks,
                                          int wm, int wn,
                                          uint32_t a_lane_off, uint32_t b_lane_off) {
#pragma unroll
    for (int mt = 0; mt < 4; mt++) {
        ldsm_x4(af[mt], sA + (uint32_t)((wm * 64 + mt * 16) * A_ROW_B + ks * 32)
                        + a_lane_off);
    }
#pragma unroll
    for (int nt = 0; nt < 8; nt++) {
        ldsm_x2_t(bf[nt], sB + (uint32_t)(ks * 16 * B_ROW_B +
                                          (wn * 64 + nt * 8) * 2) + b_lane_off);
    }
}

// -------- GEMM: C[row,n] = sum_k A[row,k]*W[m,k,n] + bias[m,n] (fp16 in, fp32 out)
// 128 threads = 4 warps (2m x 2n), warp tile 64x64, 2 CTAs/SM,
// BK=64 (half the barriers) + double-buffered fragments (LDSM under MMA).
__launch_bounds__(NTHREADS, 2)
__global__ void gemm_f16(const __half* __restrict__ A,
                         const __half* __restrict__ W,
                         const float* __restrict__ bias,
                         float* __restrict__ C,
                         int K, int Ntot, int NT) {
    extern __shared__ __align__(16) char smc[];
    const uint32_t sbase = smem_u32(smc);

    const int tid  = threadIdx.x;
    const int lane = tid & 31;
    const int warp = tid >> 5;
    const int wm   = warp >> 1;      // 0..1
    const int wn   = warp & 1;       // 0..1
    const int g    = lane >> 2;      // 0..7
    const int r    = lane & 3;       // 0..3

    const int brow   = blockIdx.y * BM;
    const int bcol   = blockIdx.x * BN;
    const int member = brow >> 12;

    const __half* Ag0 = A + (size_t)brow * K;
    const __half* Bg0 = W + (size_t)member * K * Ntot + bcol;

    float acc[4][8][4];
#pragma unroll
    for (int i = 0; i < 4; i++)
#pragma unroll
        for (int j = 0; j < 8; j++)
#pragma unroll
            for (int c = 0; c < 4; c++) acc[i][j][c] = 0.f;

    const uint32_t a_lane_off =
        (uint32_t)((lane & 15) * A_ROW_B + (lane >> 4) * 16);
    const uint32_t b_lane_off = (uint32_t)((lane & 15) * B_ROW_B);

    // prologue: stages 0,1
#pragma unroll
    for (int s = 0; s < STAGES - 1; s++) {
        load_stage(sbase, s, Ag0 + s * BK, Bg0 + (size_t)s * BK * Ntot,
                   K, Ntot, tid);
        cp_commit();
    }

    int cs = 0;            // compute stage for tile t
    int ls = STAGES - 1;   // stage receiving tile t+2

    uint32_t af[2][4][4];
    uint32_t bf[2][8][2];

    for (int t = 0; t < NT; t++) {
        cp_wait1();
        __syncthreads();

        const int u = t + STAGES - 1;
        if (u < NT) {
            load_stage(sbase, ls, Ag0 + u * BK,
                       Bg0 + (size_t)u * BK * Ntot, K, Ntot, tid);
        }
        cp_commit();

        const uint32_t sA = sbase + cs * STAGE_B;
        const uint32_t sB = sA + A_ST_B;

        // software-pipelined ks loop: prefetch ks+1 frags before ks MMAs
        frag_load(af[0], bf[0], sA, sB, 0, wm, wn, a_lane_off, b_lane_off);
#pragma unroll
        for (int ks = 0; ks < 4; ks++) {
            const int cur = ks & 1;
            if (ks < 3) {
                frag_load(af[cur ^ 1], bf[cur ^ 1], sA, sB, ks + 1,
                          wm, wn, a_lane_off, b_lane_off);
            }
#pragma unroll
            for (int mt = 0; mt < 4; mt++)
#pragma unroll
                for (int nt = 0; nt < 8; nt++)
                    mma_f16(acc[mt][nt], af[cur][mt], bf[cur][nt]);
        }

        cs = (cs == STAGES - 1) ? 0 : cs + 1;
        ls = (ls == STAGES - 1) ? 0 : ls + 1;
    }

    // epilogue: bias + store fp32
    const float* bm = bias + (size_t)member * Ntot + bcol;
#pragma unroll
    for (int mt = 0; mt < 4; mt++) {
        const int row0 = brow + wm * 64 + mt * 16 + g;
#pragma unroll
        for (int nt = 0; nt < 8; nt++) {
            const int col0 = bcol + wn * 64 + nt * 8 + r * 2;
            const float bx0 = __ldg(bm + (col0 - bcol));
            const float bx1 = __ldg(bm + (col0 - bcol) + 1);
            float2 v0, v1;
            v0.x = acc[mt][nt][0] + bx0;
            v0.y = acc[mt][nt][1] + bx1;
            v1.x = acc[mt][nt][2] + bx0;
            v1.y = acc[mt][nt][3] + bx1;
            *(float2*)(C + (size_t)row0 * Ntot + col0) = v0;
            *(float2*)(C + (size_t)(row0 + 8) * Ntot + col0) = v1;
        }
    }
}

// ---------------- pre-pass: all three fp32 -> fp16 conversions, one launch ----
#define XN8  (ROWS * E_DIM / 8)
#define W1N8 (MEMB * E_DIM * H_DIM / 8)
#define W2N8 (MEMB * H_DIM * V_DIM / 8)

__global__ void convert_all(const float* __restrict__ x,
                            const float* __restrict__ W1,
                            const float* __restrict__ W2) {
    int i = blockIdx.x * blockDim.x + threadIdx.x;
    const float* src;
    __half* dst;
    if (i < XN8) {
        src = x; dst = g_xh;
    } else if (i < XN8 + W1N8) {
        i -= XN8; src = W1; dst = g_w1h;
    } else {
        i -= XN8 + W1N8;
        if (i >= W2N8) return;
        src = W2; dst = g_w2h;
    }
    float4 a = ((const float4*)src)[2 * i];
    float4 b = ((const float4*)src)[2 * i + 1];
    __half2 h[4];
    h[0] = __floats2half2_rn(a.x, a.y);
    h[1] = __floats2half2_rn(a.z, a.w);
    h[2] = __floats2half2_rn(b.x, b.y);
    h[3] = __floats2half2_rn(b.z, b.w);
    ((uint4*)dst)[i] = *(uint4*)h;
}

// ------------- fused LayerNorm + SiLU; fp32 in (g_h), fp16 out (g_hh) -------
__launch_bounds__(256)
__global__ void ln_silu_kernel(const float* __restrict__ ln_w,
                               const float* __restrict__ ln_b) {
    const int row = blockIdx.x;
    const int m   = row >> 12;
    const float* hp = g_h + (size_t)row * H_DIM;
    __half* op = g_hh + (size_t)row * H_DIM;
    const int t = threadIdx.x;

    float4 x = *(const float4*)(hp + t * 4);
    float s = x.x + x.y + x.z + x.w;
    float q = x.x * x.x + x.y * x.y + x.z * x.z + x.w * x.w;
#pragma unroll
    for (int o = 16; o; o >>= 1) {
        s += __shfl_xor_sync(0xffffffffu, s, o);
        q += __shfl_xor_sync(0xffffffffu, q, o);
    }
    __shared__ float rs[8], rq[8];
    if ((t & 31) == 0) { rs[t >> 5] = s; rq[t >> 5] = q; }
    __syncthreads();
    s = rs[0] + rs[1] + rs[2] + rs[3] + rs[4] + rs[5] + rs[6] + rs[7];
    q = rq[0] + rq[1] + rq[2] + rq[3] + rq[4] + rq[5] + rq[6] + rq[7];

    const float mu  = s * (1.0f / H_DIM);
    const float var = q * (1.0f / H_DIM) - mu * mu;
    const float inv = rsqrtf(var + 1e-5f);

    const float4 w = *(const float4*)(ln_w + (size_t)m * H_DIM + t * 4);
    const float4 b = *(const float4*)(ln_b + (size_t)m * H_DIM + t * 4);

    float y[4]; float v;
    v = (x.x - mu) * inv * w.x + b.x; y[0] = v / (1.f + __expf(-v));
    v = (x.y - mu) * inv * w.y + b.y; y[1] = v / (1.f + __expf(-v));
    v = (x.z - mu) * inv * w.z + b.z; y[2] = v / (1.f + __expf(-v));
    v = (x.w - mu) * inv * w.w + b.w; y[3] = v / (1.f + __expf(-v));
    __half2 h2[2];
    h2[0] = __floats2half2_rn(y[0], y[1]);
    h2[1] = __floats2half2_rn(y[2], y[3]);
    *(uint2*)(op + t * 4) = *(uint2*)h2;
}

// ---------------- launch ----------------
extern "C" void kernel_launch(void* const* d_in, const int* in_sizes, int n_in,
                              void* d_out, int out_size) {
    const float* x  = (const float*)d_in[0];
    const float* W1 = (const float*)d_in[1];
    const float* b1 = (const float*)d_in[2];
    const float* lw = (const float*)d_in[3];
    const float* lb = (const float*)d_in[4];
    const float* W2 = (const float*)d_in[5];
    const float* b2 = (const float*)d_in[6];
    float* out = (float*)d_out;

    __half *xh, *w1h, *w2h, *hh;
    float* h;
    cudaGetSymbolAddress((void**)&xh,  g_xh);
    cudaGetSymbolAddress((void**)&w1h, g_w1h);
    cudaGetSymbolAddress((void**)&w2h, g_w2h);
    cudaGetSymbolAddress((void**)&h,   g_h);
    cudaGetSymbolAddress((void**)&hh,  g_hh);

    cudaFuncSetAttribute(gemm_f16, cudaFuncAttributeMaxDynamicSharedMemorySize,
                         SMEM_TOTAL);

    // pre-pass: fp32 -> fp16 (x, W1, W2 in one launch)
    const int total8 = XN8 + W1N8 + W2N8;
    convert_all<<<(total8 + 255) / 256, 256>>>(x, W1, W2);

    // GEMM1: [32768,512] x [8: 512->1024] -> h (+b1), fp32 out
    gemm_f16<<<dim3(H_DIM / BN, ROWS / BM), NTHREADS, SMEM_TOTAL>>>(
        xh, w1h, b1, h, E_DIM, H_DIM, E_DIM / BK);
    // LayerNorm + SiLU, fp16 out
    ln_silu_kernel<<<ROWS, 256>>>(lw, lb);
    // GEMM2: [32768,1024] x [8: 1024->4096] -> out (+b2)
    gemm_f16<<<dim3(V_DIM / BN, ROWS / BM), NTHREADS, SMEM_TOTAL>>>(
        hh, w2h, b2, out, H_DIM, V_DIM, H_DIM / BK);
}

// round 10
// speedup vs baseline: 2.3392x; 1.0339x over previous
#include <cuda_runtime.h>
#include <cuda_fp16.h>
#include <cstdint>
#include <cstddef>

#define MEMB   8
#define BATCHI 4096
#define E_DIM  512
#define H_DIM  1024
#define V_DIM  4096
#define ROWS   (MEMB * BATCHI)   // 32768

// ---------------- scratch (device globals: allocation-free) ----------------
__device__ __half g_xh [(size_t)ROWS * E_DIM];          // fp16 x
__device__ __half g_w1h[(size_t)MEMB * E_DIM * H_DIM];  // fp16 W1
__device__ __half g_w2h[(size_t)MEMB * H_DIM * V_DIM];  // fp16 W2
__device__ __half g_h16[(size_t)ROWS * H_DIM];          // fp16 hidden (pre-LN)
__device__ __half g_hh [(size_t)ROWS * H_DIM];          // fp16 hidden (GEMM2 in)

// ---------------- helpers ----------------
__device__ __forceinline__ uint32_t smem_u32(const void* p) {
    uint32_t a;
    asm("{ .reg .u64 t; cvta.to.shared.u64 t, %1; cvt.u32.u64 %0, t; }"
        : "=r"(a) : "l"(p));
    return a;
}
__device__ __forceinline__ void cp16(uint32_t s, const void* g) {
    asm volatile("cp.async.cg.shared.global [%0], [%1], 16;" :: "r"(s), "l"(g));
}
__device__ __forceinline__ void cp_commit() {
    asm volatile("cp.async.commit_group;" ::: "memory");
}
__device__ __forceinline__ void cp_wait1() {
    asm volatile("cp.async.wait_group 1;" ::: "memory");
}
__device__ __forceinline__ void ldsm_x4(uint32_t (&r)[4], uint32_t addr) {
    asm volatile("ldmatrix.sync.aligned.m8n8.x4.shared.b16 {%0,%1,%2,%3}, [%4];"
                 : "=r"(r[0]), "=r"(r[1]), "=r"(r[2]), "=r"(r[3]) : "r"(addr));
}
__device__ __forceinline__ void ldsm_x2_t(uint32_t (&r)[2], uint32_t addr) {
    asm volatile("ldmatrix.sync.aligned.m8n8.x2.trans.shared.b16 {%0,%1}, [%2];"
                 : "=r"(r[0]), "=r"(r[1]) : "r"(addr));
}
__device__ __forceinline__ void mma_f16(float (&d)[4], const uint32_t (&a)[4],
                                        const uint32_t (&b)[2]) {
    asm volatile(
        "mma.sync.aligned.m16n8k16.row.col.f32.f16.f16.f32 "
        "{%0,%1,%2,%3}, {%4,%5,%6,%7}, {%8,%9}, {%0,%1,%2,%3};\n"
        : "+f"(d[0]), "+f"(d[1]), "+f"(d[2]), "+f"(d[3])
        : "r"(a[0]), "r"(a[1]), "r"(a[2]), "r"(a[3]), "r"(b[0]), "r"(b[1]));
}

// ---------------- tiling ----------------
#define BM   128
#define BN   128
#define BK   64            // fp16 k-depth per tile (4 ks steps of 16)
#define NTHREADS 128       // 4 warps (2m x 2n), warp tile 64x64
#define STAGES 3
#define A_ROW_B  144       // 64 halfs (128B) + 16B pad, conflict-free ldmatrix
#define B_ROW_B  272       // 128 halfs (256B) + 16B pad, conflict-free ldmatrix
#define A_ST_B   (BM * A_ROW_B)              // 18432
#define B_ST_B   (BK * B_ROW_B)              // 17408
#define STAGE_B  (A_ST_B + B_ST_B)           // 35840
#define SMEM_TOTAL (STAGES * STAGE_B)        // 107520 (x2 CTA = 215040)
#define A_CHUNKS (BM * BK * 2 / 16)          // 1024
#define B_CHUNKS (BK * BN * 2 / 16)          // 1024

// one stage of cp.async: 16 chunks/thread @ 128 threads
__device__ __forceinline__ void load_stage(uint32_t sbase, int st,
                                           const __half* __restrict__ Ag,
                                           const __half* __restrict__ Bg,
                                           int K, int Ntot, int tid) {
    const uint32_t sA = sbase + st * STAGE_B;
    const uint32_t sB = sA + A_ST_B;
#pragma unroll
    for (int j = 0; j < (A_CHUNKS + B_CHUNKS) / NTHREADS; j++) {
        const int c = tid + j * NTHREADS;
        if (c < A_CHUNKS) {
            const int row = c >> 3, q = c & 7;        // 8 chunks per A row
            cp16(sA + (uint32_t)(row * A_ROW_B + q * 16),
                 Ag + (size_t)row * K + q * 8);
        } else {
            const int b = c - A_CHUNKS;
            const int k = b >> 4, q = b & 15;         // 16 chunks per B row
            cp16(sB + (uint32_t)(k * B_ROW_B + q * 16),
                 Bg + (size_t)k * Ntot + q * 8);
        }
    }
}

// load one ks-step's fragments (warp tile 64x64)
__device__ __forceinline__ void frag_load(uint32_t (&af)[4][4], uint32_t (&bf)[8][2],
                                          uint32_t sA, uint32_t sB, int ks,
                                          int wm, int wn,
                                          uint32_t a_lane_off, uint32_t b_lane_off) {
#pragma unroll
    for (int mt = 0; mt < 4; mt++) {
        ldsm_x4(af[mt], sA + (uint32_t)((wm * 64 + mt * 16) * A_ROW_B + ks * 32)
                        + a_lane_off);
    }
#pragma unroll
    for (int nt = 0; nt < 8; nt++) {
        ldsm_x2_t(bf[nt], sB + (uint32_t)(ks * 16 * B_ROW_B +
                                          (wn * 64 + nt * 8) * 2) + b_lane_off);
    }
}

// -------- GEMM: C[row,n] = sum_k A[row,k]*W[m,k,n] + bias[m,n] (fp16 in)
// HALF_OUT=1 -> fp16 output (GEMM1), else fp32 (GEMM2).
// 128 threads = 4 warps (2m x 2n), warp tile 64x64, 2 CTAs/SM,
// BK=64 + double-buffered fragments; ks0 LDSM issued before cp.async.
template <int HALF_OUT>
__launch_bounds__(NTHREADS, 2)
__global__ void gemm_f16(const __half* __restrict__ A,
                         const __half* __restrict__ W,
                         const float* __restrict__ bias,
                         float* __restrict__ Cf,
                         __half* __restrict__ Ch,
                         int K, int Ntot, int NT) {
    extern __shared__ __align__(16) char smc[];
    const uint32_t sbase = smem_u32(smc);

    const int tid  = threadIdx.x;
    const int lane = tid & 31;
    const int warp = tid >> 5;
    const int wm   = warp >> 1;      // 0..1
    const int wn   = warp & 1;       // 0..1
    const int g    = lane >> 2;      // 0..7
    const int r    = lane & 3;       // 0..3

    const int brow   = blockIdx.y * BM;
    const int bcol   = blockIdx.x * BN;
    const int member = brow >> 12;

    const __half* Ag0 = A + (size_t)brow * K;
    const __half* Bg0 = W + (size_t)member * K * Ntot + bcol;

    float acc[4][8][4];
#pragma unroll
    for (int i = 0; i < 4; i++)
#pragma unroll
        for (int j = 0; j < 8; j++)
#pragma unroll
            for (int c = 0; c < 4; c++) acc[i][j][c] = 0.f;

    const uint32_t a_lane_off =
        (uint32_t)((lane & 15) * A_ROW_B + (lane >> 4) * 16);
    const uint32_t b_lane_off = (uint32_t)((lane & 15) * B_ROW_B);

    // prologue: stages 0,1
#pragma unroll
    for (int s = 0; s < STAGES - 1; s++) {
        load_stage(sbase, s, Ag0 + s * BK, Bg0 + (size_t)s * BK * Ntot,
                   K, Ntot, tid);
        cp_commit();
    }

    int cs = 0;            // compute stage for tile t
    int ls = STAGES - 1;   // stage receiving tile t+2

    uint32_t af[2][4][4];
    uint32_t bf[2][8][2];

    for (int t = 0; t < NT; t++) {
        cp_wait1();
        __syncthreads();

        const uint32_t sA = sbase + cs * STAGE_B;
        const uint32_t sB = sA + A_ST_B;

        // issue ks0 LDSM first: latency hides under cp.async issue below
        frag_load(af[0], bf[0], sA, sB, 0, wm, wn, a_lane_off, b_lane_off);

        const int u = t + STAGES - 1;
        if (u < NT) {
            load_stage(sbase, ls, Ag0 + u * BK,
                       Bg0 + (size_t)u * BK * Ntot, K, Ntot, tid);
        }
        cp_commit();

        // software-pipelined ks loop: prefetch ks+1 frags before ks MMAs
#pragma unroll
        for (int ks = 0; ks < 4; ks++) {
            const int cur = ks & 1;
            if (ks < 3) {
                frag_load(af[cur ^ 1], bf[cur ^ 1], sA, sB, ks + 1,
                          wm, wn, a_lane_off, b_lane_off);
            }
#pragma unroll
            for (int mt = 0; mt < 4; mt++)
#pragma unroll
                for (int nt = 0; nt < 8; nt++)
                    mma_f16(acc[mt][nt], af[cur][mt], bf[cur][nt]);
        }

        cs = (cs == STAGES - 1) ? 0 : cs + 1;
        ls = (ls == STAGES - 1) ? 0 : ls + 1;
    }

    // epilogue: bias + store
    const float* bm = bias + (size_t)member * Ntot + bcol;
#pragma unroll
    for (int mt = 0; mt < 4; mt++) {
        const int row0 = brow + wm * 64 + mt * 16 + g;
#pragma unroll
        for (int nt = 0; nt < 8; nt++) {
            const int col0 = bcol + wn * 64 + nt * 8 + r * 2;
            const float bx0 = __ldg(bm + (col0 - bcol));
            const float bx1 = __ldg(bm + (col0 - bcol) + 1);
            if (HALF_OUT) {
                __half2 v0 = __floats2half2_rn(acc[mt][nt][0] + bx0,
                                               acc[mt][nt][1] + bx1);
                __half2 v1 = __floats2half2_rn(acc[mt][nt][2] + bx0,
                                               acc[mt][nt][3] + bx1);
                *(__half2*)(Ch + (size_t)row0 * Ntot + col0) = v0;
                *(__half2*)(Ch + (size_t)(row0 + 8) * Ntot + col0) = v1;
            } else {
                float2 v0, v1;
                v0.x = acc[mt][nt][0] + bx0;
                v0.y = acc[mt][nt][1] + bx1;
                v1.x = acc[mt][nt][2] + bx0;
                v1.y = acc[mt][nt][3] + bx1;
                *(float2*)(Cf + (size_t)row0 * Ntot + col0) = v0;
                *(float2*)(Cf + (size_t)(row0 + 8) * Ntot + col0) = v1;
            }
        }
    }
}

// ---------------- pre-pass: all three fp32 -> fp16 conversions, one launch ----
#define XN8  (ROWS * E_DIM / 8)
#define W1N8 (MEMB * E_DIM * H_DIM / 8)
#define W2N8 (MEMB * H_DIM * V_DIM / 8)

__global__ void convert_all(const float* __restrict__ x,
                            const float* __restrict__ W1,
                            const float* __restrict__ W2) {
    int i = blockIdx.x * blockDim.x + threadIdx.x;
    const float* src;
    __half* dst;
    if (i < XN8) {
        src = x; dst = g_xh;
    } else if (i < XN8 + W1N8) {
        i -= XN8; src = W1; dst = g_w1h;
    } else {
        i -= XN8 + W1N8;
        if (i >= W2N8) return;
        src = W2; dst = g_w2h;
    }
    float4 a = ((const float4*)src)[2 * i];
    float4 b = ((const float4*)src)[2 * i + 1];
    __half2 h[4];
    h[0] = __floats2half2_rn(a.x, a.y);
    h[1] = __floats2half2_rn(a.z, a.w);
    h[2] = __floats2half2_rn(b.x, b.y);
    h[3] = __floats2half2_rn(b.z, b.w);
    ((uint4*)dst)[i] = *(uint4*)h;
}

// ------------- fused LayerNorm + SiLU; fp16 in (g_h16), fp16 out (g_hh) -----
// 128 threads/row, 8 halfs/thread; stats in fp32.
__launch_bounds__(128)
__global__ void ln_silu_kernel(const float* __restrict__ ln_w,
                               const float* __restrict__ ln_b) {
    const int row = blockIdx.x;
    const int m   = row >> 12;
    const __half* hp = g_h16 + (size_t)row * H_DIM;
    __half* op = g_hh + (size_t)row * H_DIM;
    const int t = threadIdx.x;

    uint4 raw = *(const uint4*)(hp + t * 8);
    __half2 hv[4];
    *(uint4*)hv = raw;
    float xv[8];
#pragma unroll
    for (int i = 0; i < 4; i++) {
        float2 f = __half22float2(hv[i]);
        xv[2 * i] = f.x; xv[2 * i + 1] = f.y;
    }

    float s = 0.f, q = 0.f;
#pragma unroll
    for (int i = 0; i < 8; i++) { s += xv[i]; q += xv[i] * xv[i]; }
#pragma unroll
    for (int o = 16; o; o >>= 1) {
        s += __shfl_xor_sync(0xffffffffu, s, o);
        q += __shfl_xor_sync(0xffffffffu, q, o);
    }
    __shared__ float rs[4], rq[4];
    if ((t & 31) == 0) { rs[t >> 5] = s; rq[t >> 5] = q; }
    __syncthreads();
    s = rs[0] + rs[1] + rs[2] + rs[3];
    q = rq[0] + rq[1] + rq[2] + rq[3];

    const float mu  = s * (1.0f / H_DIM);
    const float var = q * (1.0f / H_DIM) - mu * mu;
    const float inv = rsqrtf(var + 1e-5f);

    const float4 w0 = *(const float4*)(ln_w + (size_t)m * H_DIM + t * 8);
    const float4 w1 = *(const float4*)(ln_w + (size_t)m * H_DIM + t * 8 + 4);
    const float4 b0 = *(const float4*)(ln_b + (size_t)m * H_DIM + t * 8);
    const float4 b1 = *(const float4*)(ln_b + (size_t)m * H_DIM + t * 8 + 4);
    const float wv[8] = {w0.x, w0.y, w0.z, w0.w, w1.x, w1.y, w1.z, w1.w};
    const float bv[8] = {b0.x, b0.y, b0.z, b0.w, b1.x, b1.y, b1.z, b1.w};

    float y[8];
#pragma unroll
    for (int i = 0; i < 8; i++) {
        float v = (xv[i] - mu) * inv * wv[i] + bv[i];
        y[i] = v / (1.f + __expf(-v));
    }
    __half2 o2[4];
#pragma unroll
    for (int i = 0; i < 4; i++) o2[i] = __floats2half2_rn(y[2 * i], y[2 * i + 1]);
    *(uint4*)(op + t * 8) = *(uint4*)o2;
}

// ---------------- launch ----------------
extern "C" void kernel_launch(void* const* d_in, const int* in_sizes, int n_in,
                              void* d_out, int out_size) {
    const float* x  = (const float*)d_in[0];
    const float* W1 = (const float*)d_in[1];
    const float* b1 = (const float*)d_in[2];
    const float* lw = (const float*)d_in[3];
    const float* lb = (const float*)d_in[4];
    const float* W2 = (const float*)d_in[5];
    const float* b2 = (const float*)d_in[6];
    float* out = (float*)d_out;

    __half *xh, *w1h, *w2h, *hh, *h16;
    cudaGetSymbolAddress((void**)&xh,  g_xh);
    cudaGetSymbolAddress((void**)&w1h, g_w1h);
    cudaGetSymbolAddress((void**)&w2h, g_w2h);
    cudaGetSymbolAddress((void**)&h16, g_h16);
    cudaGetSymbolAddress((void**)&hh,  g_hh);

    cudaFuncSetAttribute(gemm_f16<1>, cudaFuncAttributeMaxDynamicSharedMemorySize,
                         SMEM_TOTAL);
    cudaFuncSetAttribute(gemm_f16<0>, cudaFuncAttributeMaxDynamicSharedMemorySize,
                         SMEM_TOTAL);

    // pre-pass: fp32 -> fp16 (x, W1, W2 in one launch)
    const int total8 = XN8 + W1N8 + W2N8;
    convert_all<<<(total8 + 255) / 256, 256>>>(x, W1, W2);

    // GEMM1: [32768,512] x [8: 512->1024] -> h16 (+b1), fp16 out
    gemm_f16<1><<<dim3(H_DIM / BN, ROWS / BM), NTHREADS, SMEM_TOTAL>>>(
        xh, w1h, b1, nullptr, h16, E_DIM, H_DIM, E_DIM / BK);
    // LayerNorm + SiLU, fp16 -> fp16
    ln_silu_kernel<<<ROWS, 128>>>(lw, lb);
    // GEMM2: [32768,1024] x [8: 1024->4096] -> out (+b2), fp32 out
    gemm_f16<0><<<dim3(V_DIM / BN, ROWS / BM), NTHREADS, SMEM_TOTAL>>>(
        hh, w2h, b2, out, nullptr, H_DIM, V_DIM, H_DIM / BK);
}

// round 11
// speedup vs baseline: 2.3482x; 1.0038x over previous
#include <cuda_runtime.h>
#include <cuda_fp16.h>
#include <cstdint>
#include <cstddef>

#define MEMB   8
#define BATCHI 4096
#define E_DIM  512
#define H_DIM  1024
#define V_DIM  4096
#define ROWS   (MEMB * BATCHI)   // 32768

// ---------------- scratch (device globals: allocation-free) ----------------
__device__ __half g_xh [(size_t)ROWS * E_DIM];          // fp16 x
__device__ __half g_w1h[(size_t)MEMB * E_DIM * H_DIM];  // fp16 W1
__device__ __half g_w2h[(size_t)MEMB * H_DIM * V_DIM];  // fp16 W2
__device__ __half g_h16[(size_t)ROWS * H_DIM];          // fp16 hidden (pre-LN)
__device__ __half g_hh [(size_t)ROWS * H_DIM];          // fp16 hidden (GEMM2 in)

// ---------------- helpers ----------------
__device__ __forceinline__ uint32_t smem_u32(const void* p) {
    uint32_t a;
    asm("{ .reg .u64 t; cvta.to.shared.u64 t, %1; cvt.u32.u64 %0, t; }"
        : "=r"(a) : "l"(p));
    return a;
}
__device__ __forceinline__ void cp16_cg(uint32_t s, const void* g) {   // L1-bypass
    asm volatile("cp.async.cg.shared.global [%0], [%1], 16;" :: "r"(s), "l"(g));
}
__device__ __forceinline__ void cp16_ca(uint32_t s, const void* g) {   // L1-alloc
    asm volatile("cp.async.ca.shared.global [%0], [%1], 16;" :: "r"(s), "l"(g));
}
__device__ __forceinline__ void cp_commit() {
    asm volatile("cp.async.commit_group;" ::: "memory");
}
__device__ __forceinline__ void cp_wait0() {
    asm volatile("cp.async.wait_group 0;" ::: "memory");
}
__device__ __forceinline__ void ldsm_x4(uint32_t (&r)[4], uint32_t addr) {
    asm volatile("ldmatrix.sync.aligned.m8n8.x4.shared.b16 {%0,%1,%2,%3}, [%4];"
                 : "=r"(r[0]), "=r"(r[1]), "=r"(r[2]), "=r"(r[3]) : "r"(addr));
}
__device__ __forceinline__ void ldsm_x2_t(uint32_t (&r)[2], uint32_t addr) {
    asm volatile("ldmatrix.sync.aligned.m8n8.x2.trans.shared.b16 {%0,%1}, [%2];"
                 : "=r"(r[0]), "=r"(r[1]) : "r"(addr));
}
__device__ __forceinline__ void mma_f16(float (&d)[4], const uint32_t (&a)[4],
                                        const uint32_t (&b)[2]) {
    asm volatile(
        "mma.sync.aligned.m16n8k16.row.col.f32.f16.f16.f32 "
        "{%0,%1,%2,%3}, {%4,%5,%6,%7}, {%8,%9}, {%0,%1,%2,%3};\n"
        : "+f"(d[0]), "+f"(d[1]), "+f"(d[2]), "+f"(d[3])
        : "r"(a[0]), "r"(a[1]), "r"(a[2]), "r"(a[3]), "r"(b[0]), "r"(b[1]));
}

// ---------------- tiling ----------------
#define BM   128
#define BN   128
#define BK   64            // fp16 k-depth per tile (4 ks steps of 16)
#define NTHREADS 128       // 4 warps (2m x 2n), warp tile 64x64
#define STAGES 2
#define A_ROW_B  144       // 64 halfs (128B) + 16B pad, conflict-free ldmatrix
#define B_ROW_B  272       // 128 halfs (256B) + 16B pad, conflict-free ldmatrix
#define A_ST_B   (BM * A_ROW_B)              // 18432
#define B_ST_B   (BK * B_ROW_B)              // 17408
#define STAGE_B  (A_ST_B + B_ST_B)           // 35840
#define SMEM_TOTAL (STAGES * STAGE_B)        // 71680 (x2 CTA = 143360, L1 keeps ~84KB)
#define A_CHUNKS (BM * BK * 2 / 16)          // 1024
#define B_CHUNKS (BK * BN * 2 / 16)          // 1024

// one stage of cp.async: 16 chunks/thread @ 128 threads.
// A via .cg (streaming); B via .ca (L1-cached, shared with co-resident CTA).
__device__ __forceinline__ void load_stage(uint32_t sbase, int st,
                                           const __half* __restrict__ Ag,
                                           const __half* __restrict__ Bg,
                                           int K, int Ntot, int tid) {
    const uint32_t sA = sbase + st * STAGE_B;
    const uint32_t sB = sA + A_ST_B;
#pragma unroll
    for (int j = 0; j < (A_CHUNKS + B_CHUNKS) / NTHREADS; j++) {
        const int c = tid + j * NTHREADS;
        if (c < A_CHUNKS) {
            const int row = c >> 3, q = c & 7;        // 8 chunks per A row
            cp16_cg(sA + (uint32_t)(row * A_ROW_B + q * 16),
                    Ag + (size_t)row * K + q * 8);
        } else {
            const int b = c - A_CHUNKS;
            const int k = b >> 4, q = b & 15;         // 16 chunks per B row
            cp16_ca(sB + (uint32_t)(k * B_ROW_B + q * 16),
                    Bg + (size_t)k * Ntot + q * 8);
        }
    }
}

// load one ks-step's fragments (warp tile 64x64)
__device__ __forceinline__ void frag_load(uint32_t (&af)[4][4], uint32_t (&bf)[8][2],
                                          uint32_t sA, uint32_t sB, int ks,
                                          int wm, int wn,
                                          uint32_t a_lane_off, uint32_t b_lane_off) {
#pragma unroll
    for (int mt = 0; mt < 4; mt++) {
        ldsm_x4(af[mt], sA + (uint32_t)((wm * 64 + mt * 16) * A_ROW_B + ks * 32)
                        + a_lane_off);
    }
#pragma unroll
    for (int nt = 0; nt < 8; nt++) {
        ldsm_x2_t(bf[nt], sB + (uint32_t)(ks * 16 * B_ROW_B +
                                          (wn * 64 + nt * 8) * 2) + b_lane_off);
    }
}

// -------- GEMM: C[row,n] = sum_k A[row,k]*W[m,k,n] + bias[m,n] (fp16 in)
// HALF_OUT=1 -> fp16 output (GEMM1), else fp32 (GEMM2).
// grid.x = row tile (fastest) so co-resident CTAs share the same B column tile
// through L1. 128 threads = 4 warps (2m x 2n), warp tile 64x64, 2 CTAs/SM.
template <int HALF_OUT>
__launch_bounds__(NTHREADS, 2)
__global__ void gemm_f16(const __half* __restrict__ A,
                         const __half* __restrict__ W,
                         const float* __restrict__ bias,
                         float* __restrict__ Cf,
                         __half* __restrict__ Ch,
                         int K, int Ntot, int NT) {
    extern __shared__ __align__(16) char smc[];
    const uint32_t sbase = smem_u32(smc);

    const int tid  = threadIdx.x;
    const int lane = tid & 31;
    const int warp = tid >> 5;
    const int wm   = warp >> 1;      // 0..1
    const int wn   = warp & 1;       // 0..1
    const int g    = lane >> 2;      // 0..7
    const int r    = lane & 3;       // 0..3

    const int brow   = blockIdx.x * BM;   // row tile fastest
    const int bcol   = blockIdx.y * BN;
    const int member = brow >> 12;

    const __half* Ag0 = A + (size_t)brow * K;
    const __half* Bg0 = W + (size_t)member * K * Ntot + bcol;

    float acc[4][8][4];
#pragma unroll
    for (int i = 0; i < 4; i++)
#pragma unroll
        for (int j = 0; j < 8; j++)
#pragma unroll
            for (int c = 0; c < 4; c++) acc[i][j][c] = 0.f;

    const uint32_t a_lane_off =
        (uint32_t)((lane & 15) * A_ROW_B + (lane >> 4) * 16);
    const uint32_t b_lane_off = (uint32_t)((lane & 15) * B_ROW_B);

    // prologue: stage 0 = tile 0
    load_stage(sbase, 0, Ag0, Bg0, K, Ntot, tid);
    cp_commit();

    uint32_t af[2][4][4];
    uint32_t bf[2][8][2];

    for (int t = 0; t < NT; t++) {
        cp_wait0();          // tile t landed (only group pending)
        __syncthreads();     // data visible to all; all done reading other buf

        const uint32_t sA = sbase + (t & 1) * STAGE_B;
        const uint32_t sB = sA + A_ST_B;

        // ks0 LDSM first: latency hides under cp.async issue below
        frag_load(af[0], bf[0], sA, sB, 0, wm, wn, a_lane_off, b_lane_off);

        if (t + 1 < NT) {
            load_stage(sbase, (t + 1) & 1, Ag0 + (t + 1) * BK,
                       Bg0 + (size_t)(t + 1) * BK * Ntot, K, Ntot, tid);
        }
        cp_commit();

        // software-pipelined ks loop: prefetch ks+1 frags before ks MMAs
#pragma unroll
        for (int ks = 0; ks < 4; ks++) {
            const int cur = ks & 1;
            if (ks < 3) {
                frag_load(af[cur ^ 1], bf[cur ^ 1], sA, sB, ks + 1,
                          wm, wn, a_lane_off, b_lane_off);
            }
#pragma unroll
            for (int mt = 0; mt < 4; mt++)
#pragma unroll
                for (int nt = 0; nt < 8; nt++)
                    mma_f16(acc[mt][nt], af[cur][mt], bf[cur][nt]);
        }
    }

    // epilogue: bias + store
    const float* bm = bias + (size_t)member * Ntot + bcol;
#pragma unroll
    for (int mt = 0; mt < 4; mt++) {
        const int row0 = brow + wm * 64 + mt * 16 + g;
#pragma unroll
        for (int nt = 0; nt < 8; nt++) {
            const int col0 = bcol + wn * 64 + nt * 8 + r * 2;
            const float bx0 = __ldg(bm + (col0 - bcol));
            const float bx1 = __ldg(bm + (col0 - bcol) + 1);
            if (HALF_OUT) {
                __half2 v0 = __floats2half2_rn(acc[mt][nt][0] + bx0,
                                               acc[mt][nt][1] + bx1);
                __half2 v1 = __floats2half2_rn(acc[mt][nt][2] + bx0,
                                               acc[mt][nt][3] + bx1);
                *(__half2*)(Ch + (size_t)row0 * Ntot + col0) = v0;
                *(__half2*)(Ch + (size_t)(row0 + 8) * Ntot + col0) = v1;
            } else {
                float2 v0, v1;
                v0.x = acc[mt][nt][0] + bx0;
                v0.y = acc[mt][nt][1] + bx1;
                v1.x = acc[mt][nt][2] + bx0;
                v1.y = acc[mt][nt][3] + bx1;
                *(float2*)(Cf + (size_t)row0 * Ntot + col0) = v0;
                *(float2*)(Cf + (size_t)(row0 + 8) * Ntot + col0) = v1;
            }
        }
    }
}

// ---------------- pre-pass: all three fp32 -> fp16 conversions, one launch ----
#define XN8  (ROWS * E_DIM / 8)
#define W1N8 (MEMB * E_DIM * H_DIM / 8)
#define W2N8 (MEMB * H_DIM * V_DIM / 8)

__global__ void convert_all(const float* __restrict__ x,
                            const float* __restrict__ W1,
                            const float* __restrict__ W2) {
    int i = blockIdx.x * blockDim.x + threadIdx.x;
    const float* src;
    __half* dst;
    if (i < XN8) {
        src = x; dst = g_xh;
    } else if (i < XN8 + W1N8) {
        i -= XN8; src = W1; dst = g_w1h;
    } else {
        i -= XN8 + W1N8;
        if (i >= W2N8) return;
        src = W2; dst = g_w2h;
    }
    float4 a = ((const float4*)src)[2 * i];
    float4 b = ((const float4*)src)[2 * i + 1];
    __half2 h[4];
    h[0] = __floats2half2_rn(a.x, a.y);
    h[1] = __floats2half2_rn(a.z, a.w);
    h[2] = __floats2half2_rn(b.x, b.y);
    h[3] = __floats2half2_rn(b.z, b.w);
    ((uint4*)dst)[i] = *(uint4*)h;
}

// ------------- fused LayerNorm + SiLU; fp16 in (g_h16), fp16 out (g_hh) -----
// 128 threads/row, 8 halfs/thread; stats in fp32.
__launch_bounds__(128)
__global__ void ln_silu_kernel(const float* __restrict__ ln_w,
                               const float* __restrict__ ln_b) {
    const int row = blockIdx.x;
    const int m   = row >> 12;
    const __half* hp = g_h16 + (size_t)row * H_DIM;
    __half* op = g_hh + (size_t)row * H_DIM;
    const int t = threadIdx.x;

    uint4 raw = *(const uint4*)(hp + t * 8);
    __half2 hv[4];
    *(uint4*)hv = raw;
    float xv[8];
#pragma unroll
    for (int i = 0; i < 4; i++) {
        float2 f = __half22float2(hv[i]);
        xv[2 * i] = f.x; xv[2 * i + 1] = f.y;
    }

    float s = 0.f, q = 0.f;
#pragma unroll
    for (int i = 0; i < 8; i++) { s += xv[i]; q += xv[i] * xv[i]; }
#pragma unroll
    for (int o = 16; o; o >>= 1) {
        s += __shfl_xor_sync(0xffffffffu, s, o);
        q += __shfl_xor_sync(0xffffffffu, q, o);
    }
    __shared__ float rs[4], rq[4];
    if ((t & 31) == 0) { rs[t >> 5] = s; rq[t >> 5] = q; }
    __syncthreads();
    s = rs[0] + rs[1] + rs[2] + rs[3];
    q = rq[0] + rq[1] + rq[2] + rq[3];

    const float mu  = s * (1.0f / H_DIM);
    const float var = q * (1.0f / H_DIM) - mu * mu;
    const float inv = rsqrtf(var + 1e-5f);

    const float4 w0 = *(const float4*)(ln_w + (size_t)m * H_DIM + t * 8);
    const float4 w1 = *(const float4*)(ln_w + (size_t)m * H_DIM + t * 8 + 4);
    const float4 b0 = *(const float4*)(ln_b + (size_t)m * H_DIM + t * 8);
    const float4 b1 = *(const float4*)(ln_b + (size_t)m * H_DIM + t * 8 + 4);
    const float wv[8] = {w0.x, w0.y, w0.z, w0.w, w1.x, w1.y, w1.z, w1.w};
    const float bv[8] = {b0.x, b0.y, b0.z, b0.w, b1.x, b1.y, b1.z, b1.w};

    float y[8];
#pragma unroll
    for (int i = 0; i < 8; i++) {
        float v = (xv[i] - mu) * inv * wv[i] + bv[i];
        y[i] = v / (1.f + __expf(-v));
    }
    __half2 o2[4];
#pragma unroll
    for (int i = 0; i < 4; i++) o2[i] = __floats2half2_rn(y[2 * i], y[2 * i + 1]);
    *(uint4*)(op + t * 8) = *(uint4*)o2;
}

// ---------------- launch ----------------
extern "C" void kernel_launch(void* const* d_in, const int* in_sizes, int n_in,
                              void* d_out, int out_size) {
    const float* x  = (const float*)d_in[0];
    const float* W1 = (const float*)d_in[1];
    const float* b1 = (const float*)d_in[2];
    const float* lw = (const float*)d_in[3];
    const float* lb = (const float*)d_in[4];
    const float* W2 = (const float*)d_in[5];
    const float* b2 = (const float*)d_in[6];
    float* out = (float*)d_out;

    __half *xh, *w1h, *w2h, *hh, *h16;
    cudaGetSymbolAddress((void**)&xh,  g_xh);
    cudaGetSymbolAddress((void**)&w1h, g_w1h);
    cudaGetSymbolAddress((void**)&w2h, g_w2h);
    cudaGetSymbolAddress((void**)&h16, g_h16);
    cudaGetSymbolAddress((void**)&hh,  g_hh);

    cudaFuncSetAttribute(gemm_f16<1>, cudaFuncAttributeMaxDynamicSharedMemorySize,
                         SMEM_TOTAL);
    cudaFuncSetAttribute(gemm_f16<0>, cudaFuncAttributeMaxDynamicSharedMemorySize,
                         SMEM_TOTAL);

    // pre-pass: fp32 -> fp16 (x, W1, W2 in one launch)
    const int total8 = XN8 + W1N8 + W2N8;
    convert_all<<<(total8 + 255) / 256, 256>>>(x, W1, W2);

    // GEMM1: [32768,512] x [8: 512->1024] -> h16 (+b1), fp16 out
    gemm_f16<1><<<dim3(ROWS / BM, H_DIM / BN), NTHREADS, SMEM_TOTAL>>>(
        xh, w1h, b1, nullptr, h16, E_DIM, H_DIM, E_DIM / BK);
    // LayerNorm + SiLU, fp16 -> fp16
    ln_silu_kernel<<<ROWS, 128>>>(lw, lb);
    // GEMM2: [32768,1024] x [8: 1024->4096] -> out (+b2), fp32 out
    gemm_f16<0><<<dim3(ROWS / BM, V_DIM / BN), NTHREADS, SMEM_TOTAL>>>(
        hh, w2h, b2, out, nullptr, H_DIM, V_DIM, H_DIM / BK);
}

// round 12
// speedup vs baseline: 2.3618x; 1.0058x over previous
#include <cuda_runtime.h>
#include <cuda_fp16.h>
#include <cstdint>
#include <cstddef>

#define MEMB   8
#define BATCHI 4096
#define E_DIM  512
#define H_DIM  1024
#define V_DIM  4096
#define ROWS   (MEMB * BATCHI)   // 32768

// ---------------- scratch (device globals: allocation-free) ----------------
__device__ __half g_xh [(size_t)ROWS * E_DIM];          // fp16 x
__device__ __half g_w1h[(size_t)MEMB * E_DIM * H_DIM];  // fp16 W1
__device__ __half g_w2h[(size_t)MEMB * H_DIM * V_DIM];  // fp16 W2
__device__ __half g_h16[(size_t)ROWS * H_DIM];          // fp16 hidden (pre-LN)
__device__ __half g_hh [(size_t)ROWS * H_DIM];          // fp16 hidden (GEMM2 in)

// ---------------- helpers ----------------
__device__ __forceinline__ uint32_t smem_u32(const void* p) {
    uint32_t a;
    asm("{ .reg .u64 t; cvta.to.shared.u64 t, %1; cvt.u32.u64 %0, t; }"
        : "=r"(a) : "l"(p));
    return a;
}
__device__ __forceinline__ void cp16_cg(uint32_t s, const void* g) {   // L1-bypass
    asm volatile("cp.async.cg.shared.global [%0], [%1], 16;" :: "r"(s), "l"(g));
}
__device__ __forceinline__ void cp16_ca(uint32_t s, const void* g) {   // L1-alloc
    asm volatile("cp.async.ca.shared.global [%0], [%1], 16;" :: "r"(s), "l"(g));
}
__device__ __forceinline__ void cp_commit() {
    asm volatile("cp.async.commit_group;" ::: "memory");
}
__device__ __forceinline__ void cp_wait0() {
    asm volatile("cp.async.wait_group 0;" ::: "memory");
}
__device__ __forceinline__ void ldsm_x4(uint32_t (&r)[4], uint32_t addr) {
    asm volatile("ldmatrix.sync.aligned.m8n8.x4.shared.b16 {%0,%1,%2,%3}, [%4];"
                 : "=r"(r[0]), "=r"(r[1]), "=r"(r[2]), "=r"(r[3]) : "r"(addr));
}
// x4 transposed: 4 matrices = two k-halves x two adjacent n-groups
__device__ __forceinline__ void ldsm_x4_t(uint32_t& r0, uint32_t& r1,
                                          uint32_t& r2, uint32_t& r3,
                                          uint32_t addr) {
    asm volatile("ldmatrix.sync.aligned.m8n8.x4.trans.shared.b16 {%0,%1,%2,%3}, [%4];"
                 : "=r"(r0), "=r"(r1), "=r"(r2), "=r"(r3) : "r"(addr));
}
__device__ __forceinline__ void mma_f16(float (&d)[4], const uint32_t (&a)[4],
                                        const uint32_t (&b)[2]) {
    asm volatile(
        "mma.sync.aligned.m16n8k16.row.col.f32.f16.f16.f32 "
        "{%0,%1,%2,%3}, {%4,%5,%6,%7}, {%8,%9}, {%0,%1,%2,%3};\n"
        : "+f"(d[0]), "+f"(d[1]), "+f"(d[2]), "+f"(d[3])
        : "r"(a[0]), "r"(a[1]), "r"(a[2]), "r"(a[3]), "r"(b[0]), "r"(b[1]));
}

// ---------------- tiling ----------------
#define BM   128
#define BN   128
#define BK   64            // fp16 k-depth per tile (4 ks steps of 16)
#define NTHREADS 128       // 4 warps (2m x 2n), warp tile 64x64
#define STAGES 2
#define A_ROW_B  144       // 64 halfs (128B) + 16B pad, conflict-free ldmatrix
#define B_ROW_B  272       // 128 halfs (256B) + 16B pad, conflict-free ldmatrix
#define A_ST_B   (BM * A_ROW_B)              // 18432
#define B_ST_B   (BK * B_ROW_B)              // 17408
#define STAGE_B  (A_ST_B + B_ST_B)           // 35840
#define SMEM_TOTAL (STAGES * STAGE_B)        // 71680 (x2 CTA = 143360)
#define A_CHUNKS (BM * BK * 2 / 16)          // 1024
#define B_CHUNKS (BK * BN * 2 / 16)          // 1024

// one stage of cp.async: 16 chunks/thread @ 128 threads.
// A via .cg (streaming); B via .ca (L1-cached, shared with co-resident CTA).
__device__ __forceinline__ void load_stage(uint32_t sbase, int st,
                                           const __half* __restrict__ Ag,
                                           const __half* __restrict__ Bg,
                                           int K, int Ntot, int tid) {
    const uint32_t sA = sbase + st * STAGE_B;
    const uint32_t sB = sA + A_ST_B;
#pragma unroll
    for (int j = 0; j < (A_CHUNKS + B_CHUNKS) / NTHREADS; j++) {
        const int c = tid + j * NTHREADS;
        if (c < A_CHUNKS) {
            const int row = c >> 3, q = c & 7;        // 8 chunks per A row
            cp16_cg(sA + (uint32_t)(row * A_ROW_B + q * 16),
                    Ag + (size_t)row * K + q * 8);
        } else {
            const int b = c - A_CHUNKS;
            const int k = b >> 4, q = b & 15;         // 16 chunks per B row
            cp16_ca(sB + (uint32_t)(k * B_ROW_B + q * 16),
                    Bg + (size_t)k * Ntot + q * 8);
        }
    }
}

// load one ks-step's fragments (warp tile 64x64); B via x4.trans (2 n-groups/instr)
__device__ __forceinline__ void frag_load(uint32_t (&af)[4][4], uint32_t (&bf)[8][2],
                                          uint32_t sA, uint32_t sB, int ks,
                                          int wm, int wn,
                                          uint32_t a_lane_off, uint32_t b_lane_off) {
#pragma unroll
    for (int mt = 0; mt < 4; mt++) {
        ldsm_x4(af[mt], sA + (uint32_t)((wm * 64 + mt * 16) * A_ROW_B + ks * 32)
                        + a_lane_off);
    }
#pragma unroll
    for (int nt2 = 0; nt2 < 4; nt2++) {
        ldsm_x4_t(bf[2 * nt2][0], bf[2 * nt2][1],
                  bf[2 * nt2 + 1][0], bf[2 * nt2 + 1][1],
                  sB + (uint32_t)(ks * 16 * B_ROW_B + (wn * 64 + nt2 * 16) * 2)
                     + b_lane_off);
    }
}

// -------- GEMM: C[row,n] = sum_k A[row,k]*W[m,k,n] + bias[m,n] (fp16 in)
// HALF_OUT=1 -> fp16 output (GEMM1), else fp32 (GEMM2).
// 128 threads = 4 warps (2m x 2n), warp tile 64x64, 2 CTAs/SM.
template <int HALF_OUT>
__launch_bounds__(NTHREADS, 2)
__global__ void gemm_f16(const __half* __restrict__ A,
                         const __half* __restrict__ W,
                         const float* __restrict__ bias,
                         float* __restrict__ Cf,
                         __half* __restrict__ Ch,
                         int K, int Ntot, int NT) {
    extern __shared__ __align__(16) char smc[];
    const uint32_t sbase = smem_u32(smc);

    const int tid  = threadIdx.x;
    const int lane = tid & 31;
    const int warp = tid >> 5;
    const int wm   = warp >> 1;      // 0..1
    const int wn   = warp & 1;       // 0..1
    const int g    = lane >> 2;      // 0..7
    const int r    = lane & 3;       // 0..3

    const int brow   = blockIdx.x * BM;   // row tile fastest
    const int bcol   = blockIdx.y * BN;
    const int member = brow >> 12;

    const __half* Ag0 = A + (size_t)brow * K;
    const __half* Bg0 = W + (size_t)member * K * Ntot + bcol;

    float acc[4][8][4];
#pragma unroll
    for (int i = 0; i < 4; i++)
#pragma unroll
        for (int j = 0; j < 8; j++)
#pragma unroll
            for (int c = 0; c < 4; c++) acc[i][j][c] = 0.f;

    const uint32_t a_lane_off =
        (uint32_t)((lane & 15) * A_ROW_B + (lane >> 4) * 16);
    const uint32_t b_lane_off =
        (uint32_t)((lane & 15) * B_ROW_B + (lane >> 4) * 16);

    // prologue: stage 0 = tile 0
    load_stage(sbase, 0, Ag0, Bg0, K, Ntot, tid);
    cp_commit();

    uint32_t af[2][4][4];
    uint32_t bf[2][8][2];

    for (int t = 0; t < NT; t++) {
        cp_wait0();          // tile t landed (only group pending)
        __syncthreads();     // data visible to all; all done reading other buf

        const uint32_t sA = sbase + (t & 1) * STAGE_B;
        const uint32_t sB = sA + A_ST_B;

        // ks0 LDSM first: latency hides under cp.async issue below
        frag_load(af[0], bf[0], sA, sB, 0, wm, wn, a_lane_off, b_lane_off);

        if (t + 1 < NT) {
            load_stage(sbase, (t + 1) & 1, Ag0 + (t + 1) * BK,
                       Bg0 + (size_t)(t + 1) * BK * Ntot, K, Ntot, tid);
        }
        cp_commit();

        // software-pipelined ks loop: prefetch ks+1 frags before ks MMAs
#pragma unroll
        for (int ks = 0; ks < 4; ks++) {
            const int cur = ks & 1;
            if (ks < 3) {
                frag_load(af[cur ^ 1], bf[cur ^ 1], sA, sB, ks + 1,
                          wm, wn, a_lane_off, b_lane_off);
            }
#pragma unroll
            for (int mt = 0; mt < 4; mt++)
#pragma unroll
                for (int nt = 0; nt < 8; nt++)
                    mma_f16(acc[mt][nt], af[cur][mt], bf[cur][nt]);
        }
    }

    // epilogue: bias + store
    const float* bm = bias + (size_t)member * Ntot + bcol;
#pragma unroll
    for (int mt = 0; mt < 4; mt++) {
        const int row0 = brow + wm * 64 + mt * 16 + g;
#pragma unroll
        for (int nt = 0; nt < 8; nt++) {
            const int col0 = bcol + wn * 64 + nt * 8 + r * 2;
            const float bx0 = __ldg(bm + (col0 - bcol));
            const float bx1 = __ldg(bm + (col0 - bcol) + 1);
            if (HALF_OUT) {
                __half2 v0 = __floats2half2_rn(acc[mt][nt][0] + bx0,
                                               acc[mt][nt][1] + bx1);
                __half2 v1 = __floats2half2_rn(acc[mt][nt][2] + bx0,
                                               acc[mt][nt][3] + bx1);
                *(__half2*)(Ch + (size_t)row0 * Ntot + col0) = v0;
                *(__half2*)(Ch + (size_t)(row0 + 8) * Ntot + col0) = v1;
            } else {
                float2 v0, v1;
                v0.x = acc[mt][nt][0] + bx0;
                v0.y = acc[mt][nt][1] + bx1;
                v1.x = acc[mt][nt][2] + bx0;
                v1.y = acc[mt][nt][3] + bx1;
                *(float2*)(Cf + (size_t)row0 * Ntot + col0) = v0;
                *(float2*)(Cf + (size_t)(row0 + 8) * Ntot + col0) = v1;
            }
        }
    }
}

// ---------------- pre-pass: all three fp32 -> fp16 conversions, one launch ----
#define XN8  (ROWS * E_DIM / 8)
#define W1N8 (MEMB * E_DIM * H_DIM / 8)
#define W2N8 (MEMB * H_DIM * V_DIM / 8)

__global__ void convert_all(const float* __restrict__ x,
                            const float* __restrict__ W1,
                            const float* __restrict__ W2) {
    int i = blockIdx.x * blockDim.x + threadIdx.x;
    const float* src;
    __half* dst;
    if (i < XN8) {
        src = x; dst = g_xh;
    } else if (i < XN8 + W1N8) {
        i -= XN8; src = W1; dst = g_w1h;
    } else {
        i -= XN8 + W1N8;
        if (i >= W2N8) return;
        src = W2; dst = g_w2h;
    }
    float4 a = ((const float4*)src)[2 * i];
    float4 b = ((const float4*)src)[2 * i + 1];
    __half2 h[4];
    h[0] = __floats2half2_rn(a.x, a.y);
    h[1] = __floats2half2_rn(a.z, a.w);
    h[2] = __floats2half2_rn(b.x, b.y);
    h[3] = __floats2half2_rn(b.z, b.w);
    ((uint4*)dst)[i] = *(uint4*)h;
}

// ------------- fused LayerNorm + SiLU; fp16 in (g_h16), fp16 out (g_hh) -----
// 128 threads/row, 8 halfs/thread; stats in fp32.
__launch_bounds__(128)
__global__ void ln_silu_kernel(const float* __restrict__ ln_w,
                               const float* __restrict__ ln_b) {
    const int row = blockIdx.x;
    const int m   = row >> 12;
    const __half* hp = g_h16 + (size_t)row * H_DIM;
    __half* op = g_hh + (size_t)row * H_DIM;
    const int t = threadIdx.x;

    uint4 raw = *(const uint4*)(hp + t * 8);
    __half2 hv[4];
    *(uint4*)hv = raw;
    float xv[8];
#pragma unroll
    for (int i = 0; i < 4; i++) {
        float2 f = __half22float2(hv[i]);
        xv[2 * i] = f.x; xv[2 * i + 1] = f.y;
    }

    float s = 0.f, q = 0.f;
#pragma unroll
    for (int i = 0; i < 8; i++) { s += xv[i]; q += xv[i] * xv[i]; }
#pragma unroll
    for (int o = 16; o; o >>= 1) {
        s += __shfl_xor_sync(0xffffffffu, s, o);
        q += __shfl_xor_sync(0xffffffffu, q, o);
    }
    __shared__ float rs[4], rq[4];
    if ((t & 31) == 0) { rs[t >> 5] = s; rq[t >> 5] = q; }
    __syncthreads();
    s = rs[0] + rs[1] + rs[2] + rs[3];
    q = rq[0] + rq[1] + rq[2] + rq[3];

    const float mu  = s * (1.0f / H_DIM);
    const float var = q * (1.0f / H_DIM) - mu * mu;
    const float inv = rsqrtf(var + 1e-5f);

    const float4 w0 = *(const float4*)(ln_w + (size_t)m * H_DIM + t * 8);
    const float4 w1 = *(const float4*)(ln_w + (size_t)m * H_DIM + t * 8 + 4);
    const float4 b0 = *(const float4*)(ln_b + (size_t)m * H_DIM + t * 8);
    const float4 b1 = *(const float4*)(ln_b + (size_t)m * H_DIM + t * 8 + 4);
    const float wv[8] = {w0.x, w0.y, w0.z, w0.w, w1.x, w1.y, w1.z, w1.w};
    const float bv[8] = {b0.x, b0.y, b0.z, b0.w, b1.x, b1.y, b1.z, b1.w};

    float y[8];
#pragma unroll
    for (int i = 0; i < 8; i++) {
        float v = (xv[i] - mu) * inv * wv[i] + bv[i];
        y[i] = v / (1.f + __expf(-v));
    }
    __half2 o2[4];
#pragma unroll
    for (int i = 0; i < 4; i++) o2[i] = __floats2half2_rn(y[2 * i], y[2 * i + 1]);
    *(uint4*)(op + t * 8) = *(uint4*)o2;
}

// ---------------- launch ----------------
extern "C" void kernel_launch(void* const* d_in, const int* in_sizes, int n_in,
                              void* d_out, int out_size) {
    const float* x  = (const float*)d_in[0];
    const float* W1 = (const float*)d_in[1];
    const float* b1 = (const float*)d_in[2];
    const float* lw = (const float*)d_in[3];
    const float* lb = (const float*)d_in[4];
    const float* W2 = (const float*)d_in[5];
    const float* b2 = (const float*)d_in[6];
    float* out = (float*)d_out;

    __half *xh, *w1h, *w2h, *hh, *h16;
    cudaGetSymbolAddress((void**)&xh,  g_xh);
    cudaGetSymbolAddress((void**)&w1h, g_w1h);
    cudaGetSymbolAddress((void**)&w2h, g_w2h);
    cudaGetSymbolAddress((void**)&h16, g_h16);
    cudaGetSymbolAddress((void**)&hh,  g_hh);

    cudaFuncSetAttribute(gemm_f16<1>, cudaFuncAttributeMaxDynamicSharedMemorySize,
                         SMEM_TOTAL);
    cudaFuncSetAttribute(gemm_f16<0>, cudaFuncAttributeMaxDynamicSharedMemorySize,
                         SMEM_TOTAL);

    // pre-pass: fp32 -> fp16 (x, W1, W2 in one launch)
    const int total8 = XN8 + W1N8 + W2N8;
    convert_all<<<(total8 + 255) / 256, 256>>>(x, W1, W2);

    // GEMM1: [32768,512] x [8: 512->1024] -> h16 (+b1), fp16 out
    gemm_f16<1><<<dim3(ROWS / BM, H_DIM / BN), NTHREADS, SMEM_TOTAL>>>(
        xh, w1h, b1, nullptr, h16, E_DIM, H_DIM, E_DIM / BK);
    // LayerNorm + SiLU, fp16 -> fp16
    ln_silu_kernel<<<ROWS, 128>>>(lw, lb);
    // GEMM2: [32768,1024] x [8: 1024->4096] -> out (+b2), fp32 out
    gemm_f16<0><<<dim3(ROWS / BM, V_DIM / BN), NTHREADS, SMEM_TOTAL>>>(
        hh, w2h, b2, out, nullptr, H_DIM, V_DIM, H_DIM / BK);
}